// round 11
// baseline (speedup 1.0000x reference)
#include <cuda_runtime.h>
#include <math.h>
#include <stdint.h>

// ---------------- problem dims ----------------
#define NB   16
#define NS   768
#define ND   384
#define NH   12
#define NDK  32
#define NFF  1024
#define NL   6
#define NML  768
#define NNC  10
#define NBS  (NB*NS)          // 12288 rows

// ---------------- scratch ----------------
#define OFF_X   ((size_t)0)
#define OFF_H   (OFF_X  + (size_t)NBS*ND)
#define OFF_Q   (OFF_H  + (size_t)NBS*ND)
#define OFF_K   (OFF_Q  + (size_t)NBS*ND)
#define OFF_V   (OFF_K  + (size_t)NBS*ND)
#define OFF_A   (OFF_V  + (size_t)NBS*ND)
#define OFF_FF  (OFF_A  + (size_t)NBS*ND)
#define OFF_PT  (OFF_FF + (size_t)NBS*NFF)
#define OFF_PS  (OFF_PT + (size_t)NBS*384)
#define OFF_PD  (OFF_PS + (size_t)4*NBS)
#define OFF_C1  (OFF_PD + (size_t)NB*4*ND)
#define OFF_C2  (OFF_C1 + (size_t)NB*ND)
#define OFF_PW  (OFF_C2 + (size_t)NB*192)
#define SCRATCH_TOTAL (OFF_PW + (size_t)384*384)

static __device__ float g_scratch[SCRATCH_TOTAL];

// ---------------- tf32 helpers ----------------
__device__ __forceinline__ float f2tf(float f) {
    uint32_t u;
    asm("cvt.rna.tf32.f32 %0, %1;" : "=r"(u) : "f"(f));
    return __uint_as_float(u);
}

__device__ __forceinline__ void mma_tf32(float* c, const float* a, const float* b) {
    asm volatile(
        "mma.sync.aligned.m16n8k8.row.col.f32.tf32.tf32.f32 "
        "{%0,%1,%2,%3}, {%4,%5,%6,%7}, {%8,%9}, {%0,%1,%2,%3};"
        : "+f"(c[0]), "+f"(c[1]), "+f"(c[2]), "+f"(c[3])
        : "r"(__float_as_uint(a[0])), "r"(__float_as_uint(a[1])),
          "r"(__float_as_uint(a[2])), "r"(__float_as_uint(a[3])),
          "r"(__float_as_uint(b[0])), "r"(__float_as_uint(b[1])));
}

// ---------------- embed ----------------
__global__ void embed_kernel(const float* __restrict__ te, const float* __restrict__ pe,
                             const int* __restrict__ ids, float* __restrict__ x) {
    int row = blockIdx.x;
    int d   = threadIdx.x;
    int s   = row % NS;
    int id  = ids[row];
    x[(size_t)row * ND + d] = te[(size_t)id * ND + d] + pe[(size_t)s * ND + d];
}

// ---------------- pool weight pack: Wp[k][h*96+j] = pw1[h][k][j] ----------------
__global__ void pack_pool_w(const float* __restrict__ pw1, float* __restrict__ Wp) {
    int idx = blockIdx.x * 256 + threadIdx.x;
    if (idx < 384 * 384) {
        int k = idx / 384, c = idx % 384;
        int h = c / 96, j = c % 96;
        Wp[idx] = pw1[((size_t)h * 384 + k) * 96 + j];
    }
}

// ---------------- layernorm (float4, 128 thr/row) ----------------
__device__ __forceinline__ float block_sum128(float v, float* red) {
    #pragma unroll
    for (int o = 16; o > 0; o >>= 1) v += __shfl_xor_sync(0xffffffffu, v, o);
    int w = threadIdx.x >> 5;
    if ((threadIdx.x & 31) == 0) red[w] = v;
    __syncthreads();
    float t = red[0] + red[1] + red[2] + red[3];
    __syncthreads();
    return t;
}

__global__ void ln_kernel(const float* __restrict__ in, float* __restrict__ out,
                          const float* __restrict__ g, const float* __restrict__ b) {
    __shared__ float red[4];
    int row = blockIdx.x;
    const float4* p = (const float4*)(in + (size_t)row * ND);
    int i = threadIdx.x;
    float4 v4 = (i < 96) ? p[i] : make_float4(0.f, 0.f, 0.f, 0.f);
    float s = v4.x + v4.y + v4.z + v4.w;
    float mean = block_sum128(s, red) * (1.f / ND);
    float vs = 0.f;
    if (i < 96) {
        float a = v4.x - mean, bb = v4.y - mean, c = v4.z - mean, d = v4.w - mean;
        vs = a * a + bb * bb + c * c + d * d;
    }
    float var = block_sum128(vs, red) * (1.f / ND);
    float inv = rsqrtf(var + 1e-5f);
    if (i < 96) {
        float4 gv = ((const float4*)g)[i];
        float4 bv = ((const float4*)b)[i];
        float4 o;
        o.x = (v4.x - mean) * inv * gv.x + bv.x;
        o.y = (v4.y - mean) * inv * gv.y + bv.y;
        o.z = (v4.z - mean) * inv * gv.z + bv.z;
        o.w = (v4.w - mean) * inv * gv.w + bv.w;
        ((float4*)(out + (size_t)row * ND))[i] = o;
    }
}

// ================= tf32 TC GEMM: 256x128 tile, BK=16, 512 threads =================
// 16 warps in 4x4, warp tile 64x32. Requires M%256==0, N%128==0, K%16==0.
// A smem fragment-major: slot(k<16,m<256) =
//   (k>>3)*2048 + (m>>4)*128 + (m&7)*16 + (((k&3)^(((m&7)>>1)&3))<<2)
//   + ((k>>2)&1)*2 + ((m>>3)&1)
// EPI: 0 none, 1 gelu, 2 residual, 3 tanh
#define GSTRIDE 136
#define GEMM_SMEM_WORDS (2*4096 + 2*16*GSTRIDE)
#define GEMM_SMEM_BYTES (GEMM_SMEM_WORDS * 4)

template<int EPI>
__global__ void __launch_bounds__(512, 1)
gemm_tc_kernel(const float* __restrict__ A, const float* __restrict__ W,
               const float* __restrict__ bias, const float* __restrict__ res,
               float* __restrict__ C, int M, int N, int K) {
    extern __shared__ __align__(16) float dsm[];
    float* As2 = dsm;                       // [2][4096]
    float* Bsf = dsm + 8192;                // [2][16][GSTRIDE]

    const int t    = threadIdx.x;
    const int lane = t & 31;
    const int warp = t >> 5;        // 0..15
    const int wr   = warp >> 2;     // warp row 0..3 (64 m each)
    const int wn   = (warp & 3) * 32;
    const int gid  = lane >> 2;
    const int tig  = lane & 3;
    const int brow = blockIdx.y * 256;
    const int bcol = blockIdx.x * 128;

    // A loader: 2 threads per row; ksel picks k in [0,8) or [8,16)
    const int ar   = t & 255;
    const int ksel = t >> 8;
    const int asw  = ((ar & 7) >> 1) & 3;
    const int amb  = ksel * 2048 + (ar >> 4) * 128 + (ar & 7) * 16 + ((ar >> 3) & 1);
    // B loader: 1 float4 per thread
    const int bkr = t >> 5;         // 0..15
    const int bc  = lane * 4;

    const int afrag = wr * 512 + gid * 16 + ((tig ^ ((gid >> 1) & 3)) << 2);

    const float* Ap = A + (size_t)(brow + ar) * K + ksel * 8;

    float acc[4][4][4];
    #pragma unroll
    for (int i = 0; i < 4; i++)
        #pragma unroll
        for (int j = 0; j < 4; j++)
            #pragma unroll
            for (int r = 0; r < 4; r++) acc[i][j][r] = 0.f;

    const int ntiles = K / 16;

    // ---- prologue: tile 0 -> buf 0 ----
    {
        float4 a0 = *(const float4*)&Ap[0];
        float4 a1 = *(const float4*)&Ap[4];
        const float* e0 = &a0.x;
        const float* e1 = &a1.x;
        #pragma unroll
        for (int j = 0; j < 4; j++) {
            int off = ((j ^ asw) << 2);
            As2[amb + off]     = f2tf(e0[j]);
            As2[amb + 2 + off] = f2tf(e1[j]);
        }
        float4 b0 = *(const float4*)&W[(size_t)bkr * N + bcol + bc];
        float4 c0;
        c0.x = f2tf(b0.x); c0.y = f2tf(b0.y); c0.z = f2tf(b0.z); c0.w = f2tf(b0.w);
        *(float4*)&Bsf[bkr * GSTRIDE + bc] = c0;
    }
    __syncthreads();

    for (int tt = 0; tt < ntiles; tt++) {
        const int cur = tt & 1;
        const int nxt = cur ^ 1;
        const bool more = (tt + 1 < ntiles);
        float4 a0, a1, b0;
        if (more) {
            const int k0 = (tt + 1) * 16;
            a0 = *(const float4*)&Ap[k0];
            a1 = *(const float4*)&Ap[k0 + 4];
            b0 = *(const float4*)&W[(size_t)(k0 + bkr) * N + bcol + bc];
        }
        const float* Ab = As2 + cur * 4096;
        const float* Bb = Bsf + cur * (16 * GSTRIDE);
        #pragma unroll
        for (int ks = 0; ks < 2; ks++) {
            float a[4][4], b[4][2];
            #pragma unroll
            for (int mt = 0; mt < 4; mt++) {
                float4 av = *(const float4*)&Ab[ks * 2048 + mt * 128 + afrag];
                a[mt][0] = av.x; a[mt][1] = av.y; a[mt][2] = av.z; a[mt][3] = av.w;
            }
            #pragma unroll
            for (int nt = 0; nt < 4; nt++) {
                const int n0 = wn + nt * 8 + gid;
                b[nt][0] = Bb[(ks * 8 + tig) * GSTRIDE + n0];
                b[nt][1] = Bb[(ks * 8 + tig + 4) * GSTRIDE + n0];
            }
            #pragma unroll
            for (int mt = 0; mt < 4; mt++)
                #pragma unroll
                for (int nt = 0; nt < 4; nt++)
                    mma_tf32(acc[mt][nt], a[mt], b[nt]);
        }
        if (more) {
            float* An = As2 + nxt * 4096;
            const float* e0 = &a0.x;
            const float* e1 = &a1.x;
            #pragma unroll
            for (int j = 0; j < 4; j++) {
                int off = ((j ^ asw) << 2);
                An[amb + off]     = f2tf(e0[j]);
                An[amb + 2 + off] = f2tf(e1[j]);
            }
            float4 c0;
            c0.x = f2tf(b0.x); c0.y = f2tf(b0.y); c0.z = f2tf(b0.z); c0.w = f2tf(b0.w);
            *(float4*)&Bsf[nxt * (16 * GSTRIDE) + bkr * GSTRIDE + bc] = c0;
        }
        __syncthreads();
    }

    // ---- epilogue ----
    const int wm = wr * 64;
    #pragma unroll
    for (int mt = 0; mt < 4; mt++) {
        const int r0 = brow + wm + mt * 16 + gid;
        #pragma unroll
        for (int nt = 0; nt < 4; nt++) {
            const int c0 = bcol + wn + nt * 8 + tig * 2;
            float bx = bias[c0], by = bias[c0 + 1];
            float v00 = acc[mt][nt][0] + bx;
            float v01 = acc[mt][nt][1] + by;
            float v10 = acc[mt][nt][2] + bx;
            float v11 = acc[mt][nt][3] + by;
            if (EPI == 1) {
                v00 = 0.5f * v00 * (1.f + erff(v00 * 0.70710678118654752f));
                v01 = 0.5f * v01 * (1.f + erff(v01 * 0.70710678118654752f));
                v10 = 0.5f * v10 * (1.f + erff(v10 * 0.70710678118654752f));
                v11 = 0.5f * v11 * (1.f + erff(v11 * 0.70710678118654752f));
            } else if (EPI == 2) {
                float2 r0v = *(const float2*)&res[(size_t)r0 * N + c0];
                float2 r1v = *(const float2*)&res[(size_t)(r0 + 8) * N + c0];
                v00 += r0v.x; v01 += r0v.y; v10 += r1v.x; v11 += r1v.y;
            } else if (EPI == 3) {
                v00 = tanhf(v00); v01 = tanhf(v01);
                v10 = tanhf(v10); v11 = tanhf(v11);
            }
            *(float2*)&C[(size_t)r0 * N + c0]       = make_float2(v00, v01);
            *(float2*)&C[(size_t)(r0 + 8) * N + c0] = make_float2(v10, v11);
        }
    }
}

// ---------------- small guarded SGEMM (classifier) ----------------
template<int EPI>
__global__ void gemm_kernel(const float* __restrict__ A, const float* __restrict__ W,
                            const float* __restrict__ bias,
                            float* __restrict__ C, int M, int N, int K) {
    __shared__ float As[16][65];
    __shared__ float Bs[16][64];
    const int brow = blockIdx.y * 64;
    const int bcol = blockIdx.x * 64;
    const int t  = threadIdx.x;
    const int ty = t >> 4, tx = t & 15;
    float acc[4][4] = {};
    for (int k0 = 0; k0 < K; k0 += 16) {
        #pragma unroll
        for (int l = t; l < 1024; l += 256) {
            int r = l >> 4, kk = l & 15;
            int gr = brow + r;
            As[kk][r] = (gr < M && k0 + kk < K) ? A[(size_t)gr * K + k0 + kk] : 0.f;
        }
        #pragma unroll
        for (int l = t; l < 1024; l += 256) {
            int kk = l >> 6, c = l & 63;
            int gc = bcol + c;
            Bs[kk][c] = (gc < N && k0 + kk < K) ? W[(size_t)(k0 + kk) * N + gc] : 0.f;
        }
        __syncthreads();
        #pragma unroll
        for (int kk = 0; kk < 16; kk++) {
            float a[4], bvals[4];
            #pragma unroll
            for (int i = 0; i < 4; i++) a[i] = As[kk][ty * 4 + i];
            #pragma unroll
            for (int j = 0; j < 4; j++) bvals[j] = Bs[kk][tx * 4 + j];
            #pragma unroll
            for (int i = 0; i < 4; i++)
                #pragma unroll
                for (int j = 0; j < 4; j++)
                    acc[i][j] += a[i] * bvals[j];
        }
        __syncthreads();
    }
    #pragma unroll
    for (int i = 0; i < 4; i++) {
        int row = brow + ty * 4 + i;
        if (row >= M) continue;
        #pragma unroll
        for (int j = 0; j < 4; j++) {
            int col = bcol + tx * 4 + j;
            if (col >= N) continue;
            float v = acc[i][j] + bias[col];
            if (EPI == 1) v = 0.5f * v * (1.f + erff(v * 0.70710678118654752f));
            else if (EPI == 3) v = tanhf(v);
            C[(size_t)row * N + col] = v;
        }
    }
}

// ================= tensor-core flash attention with banded rel bias =================
#define ATT_SMEM_WORDS 25920
#define ATT_SMEM_BYTES (ATT_SMEM_WORDS * 4)

__global__ void __launch_bounds__(256)
attn_tc_kernel(const float* __restrict__ q, const float* __restrict__ k,
               const float* __restrict__ v, const float* __restrict__ rel,
               const int* __restrict__ ids, float* __restrict__ out) {
    extern __shared__ float sm[];
    float* Qs = sm;                   // [32][132] (d-major, transposed)
    float* Ks = sm + 4224;            // [32][68]
    float* Rs = sm + 6400;            // [32][200]
    float* Vs = sm + 12800;           // [64][36]
    float* WS = sm + 15104;           // [8][16][84]
    int*   Mk = (int*)(sm + 25856);   // [64]

    const int q0 = blockIdx.x * 128;
    const int h  = blockIdx.y;
    const int b  = blockIdx.z;
    const int t    = threadIdx.x;
    const int lane = t & 31;
    const int w    = t >> 5;
    const int gid  = lane >> 2;
    const int tig  = lane & 3;
    float* WSw = WS + w * (16 * 84);
    const int j0w = 112 - 16 * w;
    const float scale = 0.17677669529663689f;

    // ---- load Q tile (transposed, tf32) ----
    {
        const float* qb = q + ((size_t)(b * NS + q0)) * ND + h * NDK;
        #pragma unroll
        for (int i = t; i < 1024; i += 256) {
            int r = i >> 3, d0 = (i & 7) * 4;
            float4 x = *(const float4*)&qb[(size_t)r * ND + d0];
            Qs[(d0 + 0) * 132 + r] = f2tf(x.x);
            Qs[(d0 + 1) * 132 + r] = f2tf(x.y);
            Qs[(d0 + 2) * 132 + r] = f2tf(x.z);
            Qs[(d0 + 3) * 132 + r] = f2tf(x.w);
        }
    }
    __syncthreads();

    // ---- Q fragments: loaded ONCE ----
    float af[4][4];
    #pragma unroll
    for (int ks = 0; ks < 4; ks++) {
        int kk = ks * 8 + tig;
        int m0 = w * 16 + gid;
        af[ks][0] = Qs[kk * 132 + m0];
        af[ks][1] = Qs[kk * 132 + m0 + 8];
        af[ks][2] = Qs[(kk + 4) * 132 + m0];
        af[ks][3] = Qs[(kk + 4) * 132 + m0 + 8];
    }

    float m_lo = -INFINITY, m_hi = -INFINITY, l_lo = 0.f, l_hi = 0.f;
    float oa[4][4];
    #pragma unroll
    for (int i = 0; i < 4; i++)
        #pragma unroll
        for (int j = 0; j < 4; j++) oa[i][j] = 0.f;

    for (int k0 = 0; k0 < NS; k0 += 64) {
        __syncthreads();
        {
            const float* kb = k + ((size_t)(b * NS + k0)) * ND + h * NDK;
            const float* vb = v + ((size_t)(b * NS + k0)) * ND + h * NDK;
            #pragma unroll
            for (int i = t; i < 512; i += 256) {
                int r = i >> 3, d0 = (i & 7) * 4;
                float4 x = *(const float4*)&kb[(size_t)r * ND + d0];
                Ks[(d0 + 0) * 68 + r] = f2tf(x.x);
                Ks[(d0 + 1) * 68 + r] = f2tf(x.y);
                Ks[(d0 + 2) * 68 + r] = f2tf(x.z);
                Ks[(d0 + 3) * 68 + r] = f2tf(x.w);
                float4 y = *(const float4*)&vb[(size_t)r * ND + d0];
                float4 z;
                z.x = f2tf(y.x); z.y = f2tf(y.y); z.z = f2tf(y.z); z.w = f2tf(y.w);
                *(float4*)&Vs[r * 36 + d0] = z;
            }
            const float* rb = rel + (size_t)(k0 - q0 + 640) * NDK;
            for (int i = t; i < 191 * 8; i += 256) {
                int j = i >> 3, d0 = (i & 7) * 4;
                float4 x = *(const float4*)&rb[(size_t)j * NDK + d0];
                Rs[(d0 + 0) * 200 + j] = f2tf(x.x);
                Rs[(d0 + 1) * 200 + j] = f2tf(x.y);
                Rs[(d0 + 2) * 200 + j] = f2tf(x.z);
                Rs[(d0 + 3) * 200 + j] = f2tf(x.w);
            }
            if (t < 64) Mk[t] = ids[b * NS + k0 + t];
        }
        __syncthreads();

        // ---- rel-band MMA: P[16 x 80] ----
        {
            float rc[10][4];
            #pragma unroll
            for (int nt = 0; nt < 10; nt++)
                #pragma unroll
                for (int e = 0; e < 4; e++) rc[nt][e] = 0.f;
            #pragma unroll
            for (int ks = 0; ks < 4; ks++) {
                int kk = ks * 8 + tig;
                #pragma unroll
                for (int nt = 0; nt < 10; nt++) {
                    int col = j0w + nt * 8 + gid;
                    float bb[2];
                    bb[0] = Rs[kk * 200 + col];
                    bb[1] = Rs[(kk + 4) * 200 + col];
                    mma_tf32(rc[nt], af[ks], bb);
                }
            }
            #pragma unroll
            for (int nt = 0; nt < 10; nt++) {
                int c0 = nt * 8 + 2 * tig;
                WSw[gid * 84 + c0]           = rc[nt][0];
                WSw[gid * 84 + c0 + 1]       = rc[nt][1];
                WSw[(gid + 8) * 84 + c0]     = rc[nt][2];
                WSw[(gid + 8) * 84 + c0 + 1] = rc[nt][3];
            }
        }
        __syncwarp();

        // ---- QK MMA: S1[16 x 64] ----
        float qa[8][4];
        #pragma unroll
        for (int nt = 0; nt < 8; nt++)
            #pragma unroll
            for (int e = 0; e < 4; e++) qa[nt][e] = 0.f;
        #pragma unroll
        for (int ks = 0; ks < 4; ks++) {
            int kk = ks * 8 + tig;
            #pragma unroll
            for (int nt = 0; nt < 8; nt++) {
                int col = nt * 8 + gid;
                float bb[2];
                bb[0] = Ks[kk * 68 + col];
                bb[1] = Ks[(kk + 4) * 68 + col];
                mma_tf32(qa[nt], af[ks], bb);
            }
        }

        // ---- combine + mask ----
        #pragma unroll
        for (int nt = 0; nt < 8; nt++) {
            int kl0 = nt * 8 + 2 * tig;
            int kl1 = kl0 + 1;
            int rlo = gid, rhi = gid + 8;
            bool m0b = (Mk[kl0] == 0), m1b = (Mk[kl1] == 0);
            qa[nt][0] = m0b ? -INFINITY : (qa[nt][0] + WSw[rlo * 84 + kl0 + 15 - rlo]) * scale;
            qa[nt][1] = m1b ? -INFINITY : (qa[nt][1] + WSw[rlo * 84 + kl1 + 15 - rlo]) * scale;
            qa[nt][2] = m0b ? -INFINITY : (qa[nt][2] + WSw[rhi * 84 + kl0 + 15 - rhi]) * scale;
            qa[nt][3] = m1b ? -INFINITY : (qa[nt][3] + WSw[rhi * 84 + kl1 + 15 - rhi]) * scale;
        }
        __syncwarp();

        // ---- online softmax ----
        float tm_lo = -INFINITY, tm_hi = -INFINITY;
        #pragma unroll
        for (int nt = 0; nt < 8; nt++) {
            tm_lo = fmaxf(tm_lo, fmaxf(qa[nt][0], qa[nt][1]));
            tm_hi = fmaxf(tm_hi, fmaxf(qa[nt][2], qa[nt][3]));
        }
        tm_lo = fmaxf(tm_lo, __shfl_xor_sync(0xffffffffu, tm_lo, 1));
        tm_lo = fmaxf(tm_lo, __shfl_xor_sync(0xffffffffu, tm_lo, 2));
        tm_hi = fmaxf(tm_hi, __shfl_xor_sync(0xffffffffu, tm_hi, 1));
        tm_hi = fmaxf(tm_hi, __shfl_xor_sync(0xffffffffu, tm_hi, 2));

        float nm_lo = fmaxf(m_lo, tm_lo);
        float nm_hi = fmaxf(m_hi, tm_hi);
        float c_lo = 1.f, c_hi = 1.f, sum_lo = 0.f, sum_hi = 0.f;

        if (nm_lo == -INFINITY) {
            #pragma unroll
            for (int nt = 0; nt < 8; nt++) {
                int c0 = nt * 8 + 2 * tig;
                WSw[gid * 84 + c0] = 0.f; WSw[gid * 84 + c0 + 1] = 0.f;
            }
        } else {
            c_lo = __expf(m_lo - nm_lo);
            #pragma unroll
            for (int nt = 0; nt < 8; nt++) {
                int c0 = nt * 8 + 2 * tig;
                float p0 = __expf(qa[nt][0] - nm_lo);
                float p1 = __expf(qa[nt][1] - nm_lo);
                sum_lo += p0 + p1;
                WSw[gid * 84 + c0]     = f2tf(p0);
                WSw[gid * 84 + c0 + 1] = f2tf(p1);
            }
        }
        if (nm_hi == -INFINITY) {
            #pragma unroll
            for (int nt = 0; nt < 8; nt++) {
                int c0 = nt * 8 + 2 * tig;
                WSw[(gid + 8) * 84 + c0] = 0.f; WSw[(gid + 8) * 84 + c0 + 1] = 0.f;
            }
        } else {
            c_hi = __expf(m_hi - nm_hi);
            #pragma unroll
            for (int nt = 0; nt < 8; nt++) {
                int c0 = nt * 8 + 2 * tig;
                float p0 = __expf(qa[nt][2] - nm_hi);
                float p1 = __expf(qa[nt][3] - nm_hi);
                sum_hi += p0 + p1;
                WSw[(gid + 8) * 84 + c0]     = f2tf(p0);
                WSw[(gid + 8) * 84 + c0 + 1] = f2tf(p1);
            }
        }
        sum_lo += __shfl_xor_sync(0xffffffffu, sum_lo, 1);
        sum_lo += __shfl_xor_sync(0xffffffffu, sum_lo, 2);
        sum_hi += __shfl_xor_sync(0xffffffffu, sum_hi, 1);
        sum_hi += __shfl_xor_sync(0xffffffffu, sum_hi, 2);
        m_lo = nm_lo; m_hi = nm_hi;
        l_lo = l_lo * c_lo + sum_lo;
        l_hi = l_hi * c_hi + sum_hi;
        #pragma unroll
        for (int nt = 0; nt < 4; nt++) {
            oa[nt][0] *= c_lo; oa[nt][1] *= c_lo;
            oa[nt][2] *= c_hi; oa[nt][3] *= c_hi;
        }
        __syncwarp();

        // ---- PV MMA: O[16 x 32] += P[16 x 64] @ V[64 x 32] ----
        #pragma unroll
        for (int ks = 0; ks < 8; ks++) {
            int kk = ks * 8 + tig;
            float pa[4];
            pa[0] = WSw[gid * 84 + kk];
            pa[1] = WSw[(gid + 8) * 84 + kk];
            pa[2] = WSw[gid * 84 + kk + 4];
            pa[3] = WSw[(gid + 8) * 84 + kk + 4];
            #pragma unroll
            for (int nt = 0; nt < 4; nt++) {
                int col = nt * 8 + gid;
                float bb[2];
                bb[0] = Vs[kk * 36 + col];
                bb[1] = Vs[(kk + 4) * 36 + col];
                mma_tf32(oa[nt], pa, bb);
            }
        }
    }

    // ---- finalize ----
    float inv_lo = (l_lo > 0.f) ? 1.f / l_lo : 0.f;
    float inv_hi = (l_hi > 0.f) ? 1.f / l_hi : 0.f;
    const int rlo = b * NS + q0 + w * 16 + gid;
    #pragma unroll
    for (int nt = 0; nt < 4; nt++) {
        int col = h * NDK + nt * 8 + 2 * tig;
        out[(size_t)rlo * ND + col]           = oa[nt][0] * inv_lo;
        out[(size_t)rlo * ND + col + 1]       = oa[nt][1] * inv_lo;
        out[(size_t)(rlo + 8) * ND + col]     = oa[nt][2] * inv_hi;
        out[(size_t)(rlo + 8) * ND + col + 1] = oa[nt][3] * inv_hi;
    }
}

// ---------------- pooling ----------------
// tmp layout: [NBS][384], head h at cols h*96..h*96+95
__global__ void pool_score_kernel(const float* __restrict__ tmp, const float* __restrict__ pw2,
                                  const float* __restrict__ pb2, float* __restrict__ scores) {
    int gid = blockIdx.x * (blockDim.x >> 5) + (threadIdx.x >> 5);
    if (gid >= 4 * NBS) return;
    int head = gid / NBS;
    int row  = gid - head * NBS;
    int lane = threadIdx.x & 31;
    const float* p = tmp + (size_t)row * 384 + head * 96;
    float s = 0.f;
    for (int j = lane; j < 96; j += 32) s += p[j] * pw2[head * 96 + j];
    #pragma unroll
    for (int o = 16; o > 0; o >>= 1) s += __shfl_xor_sync(0xffffffffu, s, o);
    if (lane == 0) scores[gid] = s + pb2[head];
}

__global__ void pool_kernel(const float* __restrict__ x, const float* __restrict__ scores,
                            const int* __restrict__ ids, float* __restrict__ pooled) {
    const int head = blockIdx.x;
    const int b    = blockIdx.y;
    __shared__ float ps[NS];
    __shared__ float red[8];
    const float* sc = scores + (size_t)head * NBS + (size_t)b * NS;

    float m = -INFINITY;
    for (int s = threadIdx.x; s < NS; s += 256) {
        float val = (ids[b * NS + s] == 0) ? -INFINITY : sc[s];
        ps[s] = val;
        m = fmaxf(m, val);
    }
    #pragma unroll
    for (int o = 16; o > 0; o >>= 1) m = fmaxf(m, __shfl_xor_sync(0xffffffffu, m, o));
    if ((threadIdx.x & 31) == 0) red[threadIdx.x >> 5] = m;
    __syncthreads();
    float M = -INFINITY;
    #pragma unroll
    for (int i = 0; i < 8; i++) M = fmaxf(M, red[i]);
    __syncthreads();

    float sum = 0.f;
    for (int s = threadIdx.x; s < NS; s += 256) {
        float p = __expf(ps[s] - M);
        ps[s] = p;
        sum += p;
    }
    #pragma unroll
    for (int o = 16; o > 0; o >>= 1) sum += __shfl_xor_sync(0xffffffffu, sum, o);
    if ((threadIdx.x & 31) == 0) red[threadIdx.x >> 5] = sum;
    __syncthreads();
    float T = 0.f;
    #pragma unroll
    for (int i = 0; i < 8; i++) T += red[i];
    __syncthreads();
    float inv = 1.f / T;

    for (int d = threadIdx.x; d < ND; d += 256) {
        float acc = 0.f;
        const float* xp = x + (size_t)b * NS * ND + d;
        for (int s = 0; s < NS; s++) acc += ps[s] * xp[(size_t)s * ND];
        pooled[(size_t)b * (4 * ND) + head * ND + d] = acc * inv;
    }
}

// ---------------- dispatchers ----------------
static void run_big_gemm(const float* A, const float* W, const float* bias, const float* res,
                         float* C, int M, int N, int K, int epi) {
    dim3 grid(N / 128, M / 256);
    switch (epi) {
        case 0: gemm_tc_kernel<0><<<grid, 512, GEMM_SMEM_BYTES>>>(A, W, bias, res, C, M, N, K); break;
        case 1: gemm_tc_kernel<1><<<grid, 512, GEMM_SMEM_BYTES>>>(A, W, bias, res, C, M, N, K); break;
        case 2: gemm_tc_kernel<2><<<grid, 512, GEMM_SMEM_BYTES>>>(A, W, bias, res, C, M, N, K); break;
        case 3: gemm_tc_kernel<3><<<grid, 512, GEMM_SMEM_BYTES>>>(A, W, bias, res, C, M, N, K); break;
    }
}

static void run_small_gemm(const float* A, const float* W, const float* bias,
                           float* C, int M, int N, int K, int epi) {
    dim3 grid((N + 63) / 64, (M + 63) / 64);
    switch (epi) {
        case 0: gemm_kernel<0><<<grid, 256>>>(A, W, bias, C, M, N, K); break;
        case 1: gemm_kernel<1><<<grid, 256>>>(A, W, bias, C, M, N, K); break;
        case 3: gemm_kernel<3><<<grid, 256>>>(A, W, bias, C, M, N, K); break;
    }
}

// ---------------- entry ----------------
extern "C" void kernel_launch(void* const* d_in, const int* in_sizes, int n_in,
                              void* d_out, int out_size) {
    const float* te   = (const float*)d_in[0];
    const float* pe   = (const float*)d_in[1];
    const float* wq   = (const float*)d_in[2];
    const float* bq   = (const float*)d_in[3];
    const float* wk   = (const float*)d_in[4];
    const float* bk   = (const float*)d_in[5];
    const float* wv   = (const float*)d_in[6];
    const float* bv   = (const float*)d_in[7];
    const float* wo   = (const float*)d_in[8];
    const float* bo   = (const float*)d_in[9];
    const float* rel  = (const float*)d_in[10];
    const float* g1   = (const float*)d_in[11];
    const float* b1   = (const float*)d_in[12];
    const float* g2   = (const float*)d_in[13];
    const float* b2   = (const float*)d_in[14];
    const float* fw1  = (const float*)d_in[15];
    const float* fb1  = (const float*)d_in[16];
    const float* fw2  = (const float*)d_in[17];
    const float* fb2  = (const float*)d_in[18];
    const float* fg   = (const float*)d_in[19];
    const float* fbn  = (const float*)d_in[20];
    const float* pw1  = (const float*)d_in[21];
    const float* pb1  = (const float*)d_in[22];
    const float* pw2  = (const float*)d_in[23];
    const float* pb2  = (const float*)d_in[24];
    const float* cw1  = (const float*)d_in[25];
    const float* cb1  = (const float*)d_in[26];
    const float* cw2  = (const float*)d_in[27];
    const float* cb2  = (const float*)d_in[28];
    const float* cw3  = (const float*)d_in[29];
    const float* cb3  = (const float*)d_in[30];
    const int*   ids  = (const int*)d_in[31];

    float* S;
    cudaGetSymbolAddress((void**)&S, g_scratch);
    float* X  = S + OFF_X;
    float* HB = S + OFF_H;
    float* Q  = S + OFF_Q;
    float* K  = S + OFF_K;
    float* V  = S + OFF_V;
    float* AB = S + OFF_A;
    float* FB = S + OFF_FF;
    float* PT = S + OFF_PT;
    float* PS = S + OFF_PS;
    float* PD = S + OFF_PD;
    float* C1 = S + OFF_C1;
    float* C2 = S + OFF_C2;
    float* PW = S + OFF_PW;

    cudaFuncSetAttribute(attn_tc_kernel,
                         cudaFuncAttributeMaxDynamicSharedMemorySize, ATT_SMEM_BYTES);
    cudaFuncSetAttribute(gemm_tc_kernel<0>,
                         cudaFuncAttributeMaxDynamicSharedMemorySize, GEMM_SMEM_BYTES);
    cudaFuncSetAttribute(gemm_tc_kernel<1>,
                         cudaFuncAttributeMaxDynamicSharedMemorySize, GEMM_SMEM_BYTES);
    cudaFuncSetAttribute(gemm_tc_kernel<2>,
                         cudaFuncAttributeMaxDynamicSharedMemorySize, GEMM_SMEM_BYTES);
    cudaFuncSetAttribute(gemm_tc_kernel<3>,
                         cudaFuncAttributeMaxDynamicSharedMemorySize, GEMM_SMEM_BYTES);

    embed_kernel<<<NBS, ND>>>(te, pe, ids, X);

    for (int l = 0; l < NL; l++) {
        const size_t wOff = (size_t)l * ND * ND;
        const size_t dOff = (size_t)l * ND;
        ln_kernel<<<NBS, 128>>>(X, HB, g1 + dOff, b1 + dOff);
        run_big_gemm(HB, wq + wOff, bq + dOff, nullptr, Q, NBS, ND, ND, 0);
        run_big_gemm(HB, wk + wOff, bk + dOff, nullptr, K, NBS, ND, ND, 0);
        run_big_gemm(HB, wv + wOff, bv + dOff, nullptr, V, NBS, ND, ND, 0);
        attn_tc_kernel<<<dim3(NS / 128, NH, NB), 256, ATT_SMEM_BYTES>>>(
            Q, K, V, rel + (size_t)l * (2 * NML - 1) * NDK, ids, AB);
        run_big_gemm(AB, wo + wOff, bo + dOff, X, X, NBS, ND, ND, 2);
        ln_kernel<<<NBS, 128>>>(X, HB, g2 + dOff, b2 + dOff);
        run_big_gemm(HB, fw1 + (size_t)l * ND * NFF, fb1 + (size_t)l * NFF, nullptr, FB,
                     NBS, NFF, ND, 1);
        run_big_gemm(FB, fw2 + (size_t)l * NFF * ND, fb2 + dOff, X, X, NBS, ND, NFF, 2);
    }

    ln_kernel<<<NBS, 128>>>(X, HB, fg, fbn);

    // pooling: pack pw1 -> [384][384], one TC gemm with tanh (pb1 is already a flat 384-bias)
    pack_pool_w<<<576, 256>>>(pw1, PW);
    run_big_gemm(HB, PW, pb1, nullptr, PT, NBS, 384, 384, 3);
    pool_score_kernel<<<(4 * NBS + 3) / 4, 128>>>(PT, pw2, pb2, PS);
    pool_kernel<<<dim3(4, NB), 256>>>(HB, PS, ids, PD);

    run_small_gemm(PD, cw1, cb1, C1, NB, ND, 4 * ND, 1);
    run_small_gemm(C1, cw2, cb2, C2, NB, 192, ND, 1);
    run_small_gemm(C2, cw3, cb3, (float*)d_out, NB, NNC, 192, 0);
}

// round 12
// speedup vs baseline: 1.0518x; 1.0518x over previous
#include <cuda_runtime.h>
#include <math.h>
#include <stdint.h>

// ---------------- problem dims ----------------
#define NB   16
#define NS   768
#define ND   384
#define NH   12
#define NDK  32
#define NFF  1024
#define NL   6
#define NML  768
#define NNC  10
#define NBS  (NB*NS)          // 12288 rows
#define QLD  1152             // fused QKV row stride

// ---------------- scratch ----------------
#define OFF_X    ((size_t)0)
#define OFF_H    (OFF_X   + (size_t)NBS*ND)
#define OFF_QKV  (OFF_H   + (size_t)NBS*ND)
#define OFF_A    (OFF_QKV + (size_t)NBS*QLD)
#define OFF_FF   (OFF_A   + (size_t)NBS*ND)
#define OFF_PT   (OFF_FF  + (size_t)NBS*NFF)
#define OFF_PS   (OFF_PT  + (size_t)NBS*384)
#define OFF_PD   (OFF_PS  + (size_t)4*NBS)
#define OFF_C1   (OFF_PD  + (size_t)NB*4*ND)
#define OFF_C2   (OFF_C1  + (size_t)NB*ND)
#define OFF_PW   (OFF_C2  + (size_t)NB*192)
#define OFF_WQKV (OFF_PW  + (size_t)384*384)
#define OFF_BQKV (OFF_WQKV + (size_t)NL*ND*QLD)
#define SCRATCH_TOTAL (OFF_BQKV + (size_t)NL*QLD)

static __device__ float g_scratch[SCRATCH_TOTAL];

// ---------------- tf32 helpers ----------------
__device__ __forceinline__ float f2tf(float f) {
    uint32_t u;
    asm("cvt.rna.tf32.f32 %0, %1;" : "=r"(u) : "f"(f));
    return __uint_as_float(u);
}

__device__ __forceinline__ void mma_tf32(float* c, const float* a, const float* b) {
    asm volatile(
        "mma.sync.aligned.m16n8k8.row.col.f32.tf32.tf32.f32 "
        "{%0,%1,%2,%3}, {%4,%5,%6,%7}, {%8,%9}, {%0,%1,%2,%3};"
        : "+f"(c[0]), "+f"(c[1]), "+f"(c[2]), "+f"(c[3])
        : "r"(__float_as_uint(a[0])), "r"(__float_as_uint(a[1])),
          "r"(__float_as_uint(a[2])), "r"(__float_as_uint(a[3])),
          "r"(__float_as_uint(b[0])), "r"(__float_as_uint(b[1])));
}

// ---------------- embed ----------------
__global__ void embed_kernel(const float* __restrict__ te, const float* __restrict__ pe,
                             const int* __restrict__ ids, float* __restrict__ x) {
    int row = blockIdx.x;
    int d   = threadIdx.x;
    int s   = row % NS;
    int id  = ids[row];
    x[(size_t)row * ND + d] = te[(size_t)id * ND + d] + pe[(size_t)s * ND + d];
}

// ---------------- weight packers ----------------
__global__ void pack_pool_w(const float* __restrict__ pw1, float* __restrict__ Wp) {
    int idx = blockIdx.x * 256 + threadIdx.x;
    if (idx < 384 * 384) {
        int k = idx / 384, c = idx % 384;
        int h = c / 96, j = c % 96;
        Wp[idx] = pw1[((size_t)h * 384 + k) * 96 + j];
    }
}

// Wqkv[l][k][c] : c<384 -> wq, <768 -> wk, else wv
__global__ void pack_qkv_w(const float* __restrict__ wq, const float* __restrict__ wk,
                           const float* __restrict__ wv, float* __restrict__ Wf) {
    int idx = blockIdx.x * 256 + threadIdx.x;
    if (idx >= NL * ND * QLD) return;
    int l   = idx / (ND * QLD);
    int rem = idx - l * (ND * QLD);
    int k   = rem / QLD;
    int c   = rem - k * QLD;
    int sel = c / ND;
    int col = c - sel * ND;
    const float* src = (sel == 0) ? wq : (sel == 1) ? wk : wv;
    Wf[idx] = src[((size_t)l * ND + k) * ND + col];
}

__global__ void pack_qkv_b(const float* __restrict__ bq, const float* __restrict__ bk,
                           const float* __restrict__ bv, float* __restrict__ Bf) {
    int idx = blockIdx.x * 256 + threadIdx.x;
    if (idx >= NL * QLD) return;
    int l = idx / QLD;
    int c = idx - l * QLD;
    int sel = c / ND;
    int col = c - sel * ND;
    const float* src = (sel == 0) ? bq : (sel == 1) ? bk : bv;
    Bf[idx] = src[l * ND + col];
}

// ---------------- layernorm (float4, 128 thr/row) ----------------
__device__ __forceinline__ float block_sum128(float v, float* red) {
    #pragma unroll
    for (int o = 16; o > 0; o >>= 1) v += __shfl_xor_sync(0xffffffffu, v, o);
    int w = threadIdx.x >> 5;
    if ((threadIdx.x & 31) == 0) red[w] = v;
    __syncthreads();
    float t = red[0] + red[1] + red[2] + red[3];
    __syncthreads();
    return t;
}

__global__ void ln_kernel(const float* __restrict__ in, float* __restrict__ out,
                          const float* __restrict__ g, const float* __restrict__ b) {
    __shared__ float red[4];
    int row = blockIdx.x;
    const float4* p = (const float4*)(in + (size_t)row * ND);
    int i = threadIdx.x;
    float4 v4 = (i < 96) ? p[i] : make_float4(0.f, 0.f, 0.f, 0.f);
    float s = v4.x + v4.y + v4.z + v4.w;
    float mean = block_sum128(s, red) * (1.f / ND);
    float vs = 0.f;
    if (i < 96) {
        float a = v4.x - mean, bb = v4.y - mean, c = v4.z - mean, d = v4.w - mean;
        vs = a * a + bb * bb + c * c + d * d;
    }
    float var = block_sum128(vs, red) * (1.f / ND);
    float inv = rsqrtf(var + 1e-5f);
    if (i < 96) {
        float4 gv = ((const float4*)g)[i];
        float4 bv = ((const float4*)b)[i];
        float4 o;
        o.x = (v4.x - mean) * inv * gv.x + bv.x;
        o.y = (v4.y - mean) * inv * gv.y + bv.y;
        o.z = (v4.z - mean) * inv * gv.z + bv.z;
        o.w = (v4.w - mean) * inv * gv.w + bv.w;
        ((float4*)(out + (size_t)row * ND))[i] = o;
    }
}

// ================= tf32 TC GEMM: 256x128 tile, BK=16, 256 threads (R8 config) =================
// 8 warps in 4x2, warp tile 64x64. Requires M%256==0, N%128==0, K%16==0.
// EPI: 0 none, 1 gelu, 2 residual, 3 tanh
#define GSTRIDE 136
#define GEMM_SMEM_WORDS (2*4096 + 2*16*GSTRIDE)
#define GEMM_SMEM_BYTES (GEMM_SMEM_WORDS * 4)

template<int EPI>
__global__ void __launch_bounds__(256, 1)
gemm_tc_kernel(const float* __restrict__ A, const float* __restrict__ W,
               const float* __restrict__ bias, const float* __restrict__ res,
               float* __restrict__ C, int M, int N, int K) {
    extern __shared__ __align__(16) float dsm[];
    float* As2 = dsm;                       // [2][4096]
    float* Bsf = dsm + 8192;                // [2][16][GSTRIDE]

    const int t    = threadIdx.x;
    const int lane = t & 31;
    const int warp = t >> 5;
    const int wn   = (warp & 1) * 64;
    const int gid  = lane >> 2;
    const int tig  = lane & 3;
    const int brow = blockIdx.y * 256;
    const int bcol = blockIdx.x * 128;

    const int ar  = t;
    const int asw = ((ar & 7) >> 1) & 3;
    const int amb = (ar >> 4) * 128 + (ar & 7) * 16 + ((ar >> 3) & 1);
    const int bkr = t >> 5;
    const int bc  = lane * 4;

    const int afrag = (warp >> 1) * 512 + gid * 16 + ((tig ^ ((gid >> 1) & 3)) << 2);

    const float* Ap = A + (size_t)(brow + ar) * K;

    float acc[4][8][4];
    #pragma unroll
    for (int i = 0; i < 4; i++)
        #pragma unroll
        for (int j = 0; j < 8; j++)
            #pragma unroll
            for (int r = 0; r < 4; r++) acc[i][j][r] = 0.f;

    const int ntiles = K / 16;

    {
        #pragma unroll
        for (int q = 0; q < 4; q++) {
            float4 aq = *(const float4*)&Ap[q * 4];
            const float* ae = &aq.x;
            int base = (q >> 1) * 2048 + amb + (q & 1) * 2;
            #pragma unroll
            for (int j = 0; j < 4; j++)
                As2[base + ((j ^ asw) << 2)] = f2tf(ae[j]);
        }
        float4 b0 = *(const float4*)&W[(size_t)bkr * N + bcol + bc];
        float4 b1 = *(const float4*)&W[(size_t)(bkr + 8) * N + bcol + bc];
        float4 c0, c1;
        c0.x = f2tf(b0.x); c0.y = f2tf(b0.y); c0.z = f2tf(b0.z); c0.w = f2tf(b0.w);
        c1.x = f2tf(b1.x); c1.y = f2tf(b1.y); c1.z = f2tf(b1.z); c1.w = f2tf(b1.w);
        *(float4*)&Bsf[bkr * GSTRIDE + bc]       = c0;
        *(float4*)&Bsf[(bkr + 8) * GSTRIDE + bc] = c1;
    }
    __syncthreads();

    for (int tt = 0; tt < ntiles; tt++) {
        const int cur = tt & 1;
        const int nxt = cur ^ 1;
        const bool more = (tt + 1 < ntiles);
        float4 apre[4], b0, b1;
        if (more) {
            const int k0 = (tt + 1) * 16;
            #pragma unroll
            for (int q = 0; q < 4; q++) apre[q] = *(const float4*)&Ap[k0 + q * 4];
            b0 = *(const float4*)&W[(size_t)(k0 + bkr) * N + bcol + bc];
            b1 = *(const float4*)&W[(size_t)(k0 + bkr + 8) * N + bcol + bc];
        }
        const float* Ab = As2 + cur * 4096;
        const float* Bb = Bsf + cur * (16 * GSTRIDE);
        #pragma unroll
        for (int ks = 0; ks < 2; ks++) {
            float a[4][4], b[8][2];
            #pragma unroll
            for (int mt = 0; mt < 4; mt++) {
                float4 av = *(const float4*)&Ab[ks * 2048 + mt * 128 + afrag];
                a[mt][0] = av.x; a[mt][1] = av.y; a[mt][2] = av.z; a[mt][3] = av.w;
            }
            #pragma unroll
            for (int nt = 0; nt < 8; nt++) {
                const int n0 = wn + nt * 8 + gid;
                b[nt][0] = Bb[(ks * 8 + tig) * GSTRIDE + n0];
                b[nt][1] = Bb[(ks * 8 + tig + 4) * GSTRIDE + n0];
            }
            #pragma unroll
            for (int mt = 0; mt < 4; mt++)
                #pragma unroll
                for (int nt = 0; nt < 8; nt++)
                    mma_tf32(acc[mt][nt], a[mt], b[nt]);
        }
        if (more) {
            float* An = As2 + nxt * 4096;
            #pragma unroll
            for (int q = 0; q < 4; q++) {
                const float* ae = &apre[q].x;
                int base = (q >> 1) * 2048 + amb + (q & 1) * 2;
                #pragma unroll
                for (int j = 0; j < 4; j++)
                    An[base + ((j ^ asw) << 2)] = f2tf(ae[j]);
            }
            float4 c0, c1;
            c0.x = f2tf(b0.x); c0.y = f2tf(b0.y); c0.z = f2tf(b0.z); c0.w = f2tf(b0.w);
            c1.x = f2tf(b1.x); c1.y = f2tf(b1.y); c1.z = f2tf(b1.z); c1.w = f2tf(b1.w);
            float* Bn = Bsf + nxt * (16 * GSTRIDE);
            *(float4*)&Bn[bkr * GSTRIDE + bc]       = c0;
            *(float4*)&Bn[(bkr + 8) * GSTRIDE + bc] = c1;
        }
        __syncthreads();
    }

    const int wm = (warp >> 1) * 64;
    #pragma unroll
    for (int mt = 0; mt < 4; mt++) {
        const int r0 = brow + wm + mt * 16 + gid;
        #pragma unroll
        for (int nt = 0; nt < 8; nt++) {
            const int c0 = bcol + wn + nt * 8 + tig * 2;
            float bx = bias[c0], by = bias[c0 + 1];
            float v00 = acc[mt][nt][0] + bx;
            float v01 = acc[mt][nt][1] + by;
            float v10 = acc[mt][nt][2] + bx;
            float v11 = acc[mt][nt][3] + by;
            if (EPI == 1) {
                v00 = 0.5f * v00 * (1.f + erff(v00 * 0.70710678118654752f));
                v01 = 0.5f * v01 * (1.f + erff(v01 * 0.70710678118654752f));
                v10 = 0.5f * v10 * (1.f + erff(v10 * 0.70710678118654752f));
                v11 = 0.5f * v11 * (1.f + erff(v11 * 0.70710678118654752f));
            } else if (EPI == 2) {
                float2 r0v = *(const float2*)&res[(size_t)r0 * N + c0];
                float2 r1v = *(const float2*)&res[(size_t)(r0 + 8) * N + c0];
                v00 += r0v.x; v01 += r0v.y; v10 += r1v.x; v11 += r1v.y;
            } else if (EPI == 3) {
                v00 = tanhf(v00); v01 = tanhf(v01);
                v10 = tanhf(v10); v11 = tanhf(v11);
            }
            *(float2*)&C[(size_t)r0 * N + c0]       = make_float2(v00, v01);
            *(float2*)&C[(size_t)(r0 + 8) * N + c0] = make_float2(v10, v11);
        }
    }
}

// ---------------- small guarded SGEMM (classifier) ----------------
template<int EPI>
__global__ void gemm_kernel(const float* __restrict__ A, const float* __restrict__ W,
                            const float* __restrict__ bias,
                            float* __restrict__ C, int M, int N, int K) {
    __shared__ float As[16][65];
    __shared__ float Bs[16][64];
    const int brow = blockIdx.y * 64;
    const int bcol = blockIdx.x * 64;
    const int t  = threadIdx.x;
    const int ty = t >> 4, tx = t & 15;
    float acc[4][4] = {};
    for (int k0 = 0; k0 < K; k0 += 16) {
        #pragma unroll
        for (int l = t; l < 1024; l += 256) {
            int r = l >> 4, kk = l & 15;
            int gr = brow + r;
            As[kk][r] = (gr < M && k0 + kk < K) ? A[(size_t)gr * K + k0 + kk] : 0.f;
        }
        #pragma unroll
        for (int l = t; l < 1024; l += 256) {
            int kk = l >> 6, c = l & 63;
            int gc = bcol + c;
            Bs[kk][c] = (gc < N && k0 + kk < K) ? W[(size_t)(k0 + kk) * N + gc] : 0.f;
        }
        __syncthreads();
        #pragma unroll
        for (int kk = 0; kk < 16; kk++) {
            float a[4], bvals[4];
            #pragma unroll
            for (int i = 0; i < 4; i++) a[i] = As[kk][ty * 4 + i];
            #pragma unroll
            for (int j = 0; j < 4; j++) bvals[j] = Bs[kk][tx * 4 + j];
            #pragma unroll
            for (int i = 0; i < 4; i++)
                #pragma unroll
                for (int j = 0; j < 4; j++)
                    acc[i][j] += a[i] * bvals[j];
        }
        __syncthreads();
    }
    #pragma unroll
    for (int i = 0; i < 4; i++) {
        int row = brow + ty * 4 + i;
        if (row >= M) continue;
        #pragma unroll
        for (int j = 0; j < 4; j++) {
            int col = bcol + tx * 4 + j;
            if (col >= N) continue;
            float v = acc[i][j] + bias[col];
            if (EPI == 1) v = 0.5f * v * (1.f + erff(v * 0.70710678118654752f));
            else if (EPI == 3) v = tanhf(v);
            C[(size_t)row * N + col] = v;
        }
    }
}

// ================= tensor-core flash attention with banded rel bias =================
// q/k/v read from the fused QKV buffer with row stride QLD.
#define ATT_SMEM_WORDS 25920
#define ATT_SMEM_BYTES (ATT_SMEM_WORDS * 4)

__global__ void __launch_bounds__(256)
attn_tc_kernel(const float* __restrict__ q, const float* __restrict__ k,
               const float* __restrict__ v, const float* __restrict__ rel,
               const int* __restrict__ ids, float* __restrict__ out) {
    extern __shared__ float sm[];
    float* Qs = sm;                   // [32][132]
    float* Ks = sm + 4224;            // [32][68]
    float* Rs = sm + 6400;            // [32][200]
    float* Vs = sm + 12800;           // [64][36]
    float* WS = sm + 15104;           // [8][16][84]
    int*   Mk = (int*)(sm + 25856);   // [64]

    const int q0 = blockIdx.x * 128;
    const int h  = blockIdx.y;
    const int b  = blockIdx.z;
    const int t    = threadIdx.x;
    const int lane = t & 31;
    const int w    = t >> 5;
    const int gid  = lane >> 2;
    const int tig  = lane & 3;
    float* WSw = WS + w * (16 * 84);
    const int j0w = 112 - 16 * w;
    const float scale = 0.17677669529663689f;

    {
        const float* qb = q + ((size_t)(b * NS + q0)) * QLD + h * NDK;
        #pragma unroll
        for (int i = t; i < 1024; i += 256) {
            int r = i >> 3, d0 = (i & 7) * 4;
            float4 x = *(const float4*)&qb[(size_t)r * QLD + d0];
            Qs[(d0 + 0) * 132 + r] = f2tf(x.x);
            Qs[(d0 + 1) * 132 + r] = f2tf(x.y);
            Qs[(d0 + 2) * 132 + r] = f2tf(x.z);
            Qs[(d0 + 3) * 132 + r] = f2tf(x.w);
        }
    }
    __syncthreads();

    float af[4][4];
    #pragma unroll
    for (int ks = 0; ks < 4; ks++) {
        int kk = ks * 8 + tig;
        int m0 = w * 16 + gid;
        af[ks][0] = Qs[kk * 132 + m0];
        af[ks][1] = Qs[kk * 132 + m0 + 8];
        af[ks][2] = Qs[(kk + 4) * 132 + m0];
        af[ks][3] = Qs[(kk + 4) * 132 + m0 + 8];
    }

    float m_lo = -INFINITY, m_hi = -INFINITY, l_lo = 0.f, l_hi = 0.f;
    float oa[4][4];
    #pragma unroll
    for (int i = 0; i < 4; i++)
        #pragma unroll
        for (int j = 0; j < 4; j++) oa[i][j] = 0.f;

    for (int k0 = 0; k0 < NS; k0 += 64) {
        __syncthreads();
        {
            const float* kb = k + ((size_t)(b * NS + k0)) * QLD + h * NDK;
            const float* vb = v + ((size_t)(b * NS + k0)) * QLD + h * NDK;
            #pragma unroll
            for (int i = t; i < 512; i += 256) {
                int r = i >> 3, d0 = (i & 7) * 4;
                float4 x = *(const float4*)&kb[(size_t)r * QLD + d0];
                Ks[(d0 + 0) * 68 + r] = f2tf(x.x);
                Ks[(d0 + 1) * 68 + r] = f2tf(x.y);
                Ks[(d0 + 2) * 68 + r] = f2tf(x.z);
                Ks[(d0 + 3) * 68 + r] = f2tf(x.w);
                float4 y = *(const float4*)&vb[(size_t)r * QLD + d0];
                float4 z;
                z.x = f2tf(y.x); z.y = f2tf(y.y); z.z = f2tf(y.z); z.w = f2tf(y.w);
                *(float4*)&Vs[r * 36 + d0] = z;
            }
            const float* rb = rel + (size_t)(k0 - q0 + 640) * NDK;
            for (int i = t; i < 191 * 8; i += 256) {
                int j = i >> 3, d0 = (i & 7) * 4;
                float4 x = *(const float4*)&rb[(size_t)j * NDK + d0];
                Rs[(d0 + 0) * 200 + j] = f2tf(x.x);
                Rs[(d0 + 1) * 200 + j] = f2tf(x.y);
                Rs[(d0 + 2) * 200 + j] = f2tf(x.z);
                Rs[(d0 + 3) * 200 + j] = f2tf(x.w);
            }
            if (t < 64) Mk[t] = ids[b * NS + k0 + t];
        }
        __syncthreads();

        // ---- rel-band MMA: P[16 x 80] ----
        {
            float rc[10][4];
            #pragma unroll
            for (int nt = 0; nt < 10; nt++)
                #pragma unroll
                for (int e = 0; e < 4; e++) rc[nt][e] = 0.f;
            #pragma unroll
            for (int ks = 0; ks < 4; ks++) {
                int kk = ks * 8 + tig;
                #pragma unroll
                for (int nt = 0; nt < 10; nt++) {
                    int col = j0w + nt * 8 + gid;
                    float bb[2];
                    bb[0] = Rs[kk * 200 + col];
                    bb[1] = Rs[(kk + 4) * 200 + col];
                    mma_tf32(rc[nt], af[ks], bb);
                }
            }
            #pragma unroll
            for (int nt = 0; nt < 10; nt++) {
                int c0 = nt * 8 + 2 * tig;
                WSw[gid * 84 + c0]           = rc[nt][0];
                WSw[gid * 84 + c0 + 1]       = rc[nt][1];
                WSw[(gid + 8) * 84 + c0]     = rc[nt][2];
                WSw[(gid + 8) * 84 + c0 + 1] = rc[nt][3];
            }
        }
        __syncwarp();

        // ---- QK MMA: S1[16 x 64] ----
        float qa[8][4];
        #pragma unroll
        for (int nt = 0; nt < 8; nt++)
            #pragma unroll
            for (int e = 0; e < 4; e++) qa[nt][e] = 0.f;
        #pragma unroll
        for (int ks = 0; ks < 4; ks++) {
            int kk = ks * 8 + tig;
            #pragma unroll
            for (int nt = 0; nt < 8; nt++) {
                int col = nt * 8 + gid;
                float bb[2];
                bb[0] = Ks[kk * 68 + col];
                bb[1] = Ks[(kk + 4) * 68 + col];
                mma_tf32(qa[nt], af[ks], bb);
            }
        }

        // ---- combine + mask ----
        #pragma unroll
        for (int nt = 0; nt < 8; nt++) {
            int kl0 = nt * 8 + 2 * tig;
            int kl1 = kl0 + 1;
            int rlo = gid, rhi = gid + 8;
            bool m0b = (Mk[kl0] == 0), m1b = (Mk[kl1] == 0);
            qa[nt][0] = m0b ? -INFINITY : (qa[nt][0] + WSw[rlo * 84 + kl0 + 15 - rlo]) * scale;
            qa[nt][1] = m1b ? -INFINITY : (qa[nt][1] + WSw[rlo * 84 + kl1 + 15 - rlo]) * scale;
            qa[nt][2] = m0b ? -INFINITY : (qa[nt][2] + WSw[rhi * 84 + kl0 + 15 - rhi]) * scale;
            qa[nt][3] = m1b ? -INFINITY : (qa[nt][3] + WSw[rhi * 84 + kl1 + 15 - rhi]) * scale;
        }
        __syncwarp();

        // ---- online softmax ----
        float tm_lo = -INFINITY, tm_hi = -INFINITY;
        #pragma unroll
        for (int nt = 0; nt < 8; nt++) {
            tm_lo = fmaxf(tm_lo, fmaxf(qa[nt][0], qa[nt][1]));
            tm_hi = fmaxf(tm_hi, fmaxf(qa[nt][2], qa[nt][3]));
        }
        tm_lo = fmaxf(tm_lo, __shfl_xor_sync(0xffffffffu, tm_lo, 1));
        tm_lo = fmaxf(tm_lo, __shfl_xor_sync(0xffffffffu, tm_lo, 2));
        tm_hi = fmaxf(tm_hi, __shfl_xor_sync(0xffffffffu, tm_hi, 1));
        tm_hi = fmaxf(tm_hi, __shfl_xor_sync(0xffffffffu, tm_hi, 2));

        float nm_lo = fmaxf(m_lo, tm_lo);
        float nm_hi = fmaxf(m_hi, tm_hi);
        float c_lo = 1.f, c_hi = 1.f, sum_lo = 0.f, sum_hi = 0.f;

        if (nm_lo == -INFINITY) {
            #pragma unroll
            for (int nt = 0; nt < 8; nt++) {
                int c0 = nt * 8 + 2 * tig;
                WSw[gid * 84 + c0] = 0.f; WSw[gid * 84 + c0 + 1] = 0.f;
            }
        } else {
            c_lo = __expf(m_lo - nm_lo);
            #pragma unroll
            for (int nt = 0; nt < 8; nt++) {
                int c0 = nt * 8 + 2 * tig;
                float p0 = __expf(qa[nt][0] - nm_lo);
                float p1 = __expf(qa[nt][1] - nm_lo);
                sum_lo += p0 + p1;
                WSw[gid * 84 + c0]     = f2tf(p0);
                WSw[gid * 84 + c0 + 1] = f2tf(p1);
            }
        }
        if (nm_hi == -INFINITY) {
            #pragma unroll
            for (int nt = 0; nt < 8; nt++) {
                int c0 = nt * 8 + 2 * tig;
                WSw[(gid + 8) * 84 + c0] = 0.f; WSw[(gid + 8) * 84 + c0 + 1] = 0.f;
            }
        } else {
            c_hi = __expf(m_hi - nm_hi);
            #pragma unroll
            for (int nt = 0; nt < 8; nt++) {
                int c0 = nt * 8 + 2 * tig;
                float p0 = __expf(qa[nt][2] - nm_hi);
                float p1 = __expf(qa[nt][3] - nm_hi);
                sum_hi += p0 + p1;
                WSw[(gid + 8) * 84 + c0]     = f2tf(p0);
                WSw[(gid + 8) * 84 + c0 + 1] = f2tf(p1);
            }
        }
        sum_lo += __shfl_xor_sync(0xffffffffu, sum_lo, 1);
        sum_lo += __shfl_xor_sync(0xffffffffu, sum_lo, 2);
        sum_hi += __shfl_xor_sync(0xffffffffu, sum_hi, 1);
        sum_hi += __shfl_xor_sync(0xffffffffu, sum_hi, 2);
        m_lo = nm_lo; m_hi = nm_hi;
        l_lo = l_lo * c_lo + sum_lo;
        l_hi = l_hi * c_hi + sum_hi;
        #pragma unroll
        for (int nt = 0; nt < 4; nt++) {
            oa[nt][0] *= c_lo; oa[nt][1] *= c_lo;
            oa[nt][2] *= c_hi; oa[nt][3] *= c_hi;
        }
        __syncwarp();

        // ---- PV MMA ----
        #pragma unroll
        for (int ks = 0; ks < 8; ks++) {
            int kk = ks * 8 + tig;
            float pa[4];
            pa[0] = WSw[gid * 84 + kk];
            pa[1] = WSw[(gid + 8) * 84 + kk];
            pa[2] = WSw[gid * 84 + kk + 4];
            pa[3] = WSw[(gid + 8) * 84 + kk + 4];
            #pragma unroll
            for (int nt = 0; nt < 4; nt++) {
                int col = nt * 8 + gid;
                float bb[2];
                bb[0] = Vs[kk * 36 + col];
                bb[1] = Vs[(kk + 4) * 36 + col];
                mma_tf32(oa[nt], pa, bb);
            }
        }
    }

    float inv_lo = (l_lo > 0.f) ? 1.f / l_lo : 0.f;
    float inv_hi = (l_hi > 0.f) ? 1.f / l_hi : 0.f;
    const int rlo = b * NS + q0 + w * 16 + gid;
    #pragma unroll
    for (int nt = 0; nt < 4; nt++) {
        int col = h * NDK + nt * 8 + 2 * tig;
        out[(size_t)rlo * ND + col]           = oa[nt][0] * inv_lo;
        out[(size_t)rlo * ND + col + 1]       = oa[nt][1] * inv_lo;
        out[(size_t)(rlo + 8) * ND + col]     = oa[nt][2] * inv_hi;
        out[(size_t)(rlo + 8) * ND + col + 1] = oa[nt][3] * inv_hi;
    }
}

// ---------------- pooling ----------------
__global__ void pool_score_kernel(const float* __restrict__ tmp, const float* __restrict__ pw2,
                                  const float* __restrict__ pb2, float* __restrict__ scores) {
    int gid = blockIdx.x * (blockDim.x >> 5) + (threadIdx.x >> 5);
    if (gid >= 4 * NBS) return;
    int head = gid / NBS;
    int row  = gid - head * NBS;
    int lane = threadIdx.x & 31;
    const float* p = tmp + (size_t)row * 384 + head * 96;
    float s = 0.f;
    for (int j = lane; j < 96; j += 32) s += p[j] * pw2[head * 96 + j];
    #pragma unroll
    for (int o = 16; o > 0; o >>= 1) s += __shfl_xor_sync(0xffffffffu, s, o);
    if (lane == 0) scores[gid] = s + pb2[head];
}

__global__ void pool_kernel(const float* __restrict__ x, const float* __restrict__ scores,
                            const int* __restrict__ ids, float* __restrict__ pooled) {
    const int head = blockIdx.x;
    const int b    = blockIdx.y;
    __shared__ float ps[NS];
    __shared__ float red[8];
    const float* sc = scores + (size_t)head * NBS + (size_t)b * NS;

    float m = -INFINITY;
    for (int s = threadIdx.x; s < NS; s += 256) {
        float val = (ids[b * NS + s] == 0) ? -INFINITY : sc[s];
        ps[s] = val;
        m = fmaxf(m, val);
    }
    #pragma unroll
    for (int o = 16; o > 0; o >>= 1) m = fmaxf(m, __shfl_xor_sync(0xffffffffu, m, o));
    if ((threadIdx.x & 31) == 0) red[threadIdx.x >> 5] = m;
    __syncthreads();
    float M = -INFINITY;
    #pragma unroll
    for (int i = 0; i < 8; i++) M = fmaxf(M, red[i]);
    __syncthreads();

    float sum = 0.f;
    for (int s = threadIdx.x; s < NS; s += 256) {
        float p = __expf(ps[s] - M);
        ps[s] = p;
        sum += p;
    }
    #pragma unroll
    for (int o = 16; o > 0; o >>= 1) sum += __shfl_xor_sync(0xffffffffu, sum, o);
    if ((threadIdx.x & 31) == 0) red[threadIdx.x >> 5] = sum;
    __syncthreads();
    float T = 0.f;
    #pragma unroll
    for (int i = 0; i < 8; i++) T += red[i];
    __syncthreads();
    float inv = 1.f / T;

    for (int d = threadIdx.x; d < ND; d += 256) {
        float acc = 0.f;
        const float* xp = x + (size_t)b * NS * ND + d;
        for (int s = 0; s < NS; s++) acc += ps[s] * xp[(size_t)s * ND];
        pooled[(size_t)b * (4 * ND) + head * ND + d] = acc * inv;
    }
}

// ---------------- dispatchers ----------------
static void run_big_gemm(const float* A, const float* W, const float* bias, const float* res,
                         float* C, int M, int N, int K, int epi) {
    dim3 grid(N / 128, M / 256);
    switch (epi) {
        case 0: gemm_tc_kernel<0><<<grid, 256, GEMM_SMEM_BYTES>>>(A, W, bias, res, C, M, N, K); break;
        case 1: gemm_tc_kernel<1><<<grid, 256, GEMM_SMEM_BYTES>>>(A, W, bias, res, C, M, N, K); break;
        case 2: gemm_tc_kernel<2><<<grid, 256, GEMM_SMEM_BYTES>>>(A, W, bias, res, C, M, N, K); break;
        case 3: gemm_tc_kernel<3><<<grid, 256, GEMM_SMEM_BYTES>>>(A, W, bias, res, C, M, N, K); break;
    }
}

static void run_small_gemm(const float* A, const float* W, const float* bias,
                           float* C, int M, int N, int K, int epi) {
    dim3 grid((N + 63) / 64, (M + 63) / 64);
    switch (epi) {
        case 0: gemm_kernel<0><<<grid, 256>>>(A, W, bias, C, M, N, K); break;
        case 1: gemm_kernel<1><<<grid, 256>>>(A, W, bias, C, M, N, K); break;
        case 3: gemm_kernel<3><<<grid, 256>>>(A, W, bias, C, M, N, K); break;
    }
}

// ---------------- entry ----------------
extern "C" void kernel_launch(void* const* d_in, const int* in_sizes, int n_in,
                              void* d_out, int out_size) {
    const float* te   = (const float*)d_in[0];
    const float* pe   = (const float*)d_in[1];
    const float* wq   = (const float*)d_in[2];
    const float* bq   = (const float*)d_in[3];
    const float* wk   = (const float*)d_in[4];
    const float* bk   = (const float*)d_in[5];
    const float* wv   = (const float*)d_in[6];
    const float* bv   = (const float*)d_in[7];
    const float* wo   = (const float*)d_in[8];
    const float* bo   = (const float*)d_in[9];
    const float* rel  = (const float*)d_in[10];
    const float* g1   = (const float*)d_in[11];
    const float* b1   = (const float*)d_in[12];
    const float* g2   = (const float*)d_in[13];
    const float* b2   = (const float*)d_in[14];
    const float* fw1  = (const float*)d_in[15];
    const float* fb1  = (const float*)d_in[16];
    const float* fw2  = (const float*)d_in[17];
    const float* fb2  = (const float*)d_in[18];
    const float* fg   = (const float*)d_in[19];
    const float* fbn  = (const float*)d_in[20];
    const float* pw1  = (const float*)d_in[21];
    const float* pb1  = (const float*)d_in[22];
    const float* pw2  = (const float*)d_in[23];
    const float* pb2  = (const float*)d_in[24];
    const float* cw1  = (const float*)d_in[25];
    const float* cb1  = (const float*)d_in[26];
    const float* cw2  = (const float*)d_in[27];
    const float* cb2  = (const float*)d_in[28];
    const float* cw3  = (const float*)d_in[29];
    const float* cb3  = (const float*)d_in[30];
    const int*   ids  = (const int*)d_in[31];

    float* S;
    cudaGetSymbolAddress((void**)&S, g_scratch);
    float* X    = S + OFF_X;
    float* HB   = S + OFF_H;
    float* QKV  = S + OFF_QKV;
    float* AB   = S + OFF_A;
    float* FB   = S + OFF_FF;
    float* PT   = S + OFF_PT;
    float* PS   = S + OFF_PS;
    float* PD   = S + OFF_PD;
    float* C1   = S + OFF_C1;
    float* C2   = S + OFF_C2;
    float* PW   = S + OFF_PW;
    float* WQKV = S + OFF_WQKV;
    float* BQKV = S + OFF_BQKV;

    cudaFuncSetAttribute(attn_tc_kernel,
                         cudaFuncAttributeMaxDynamicSharedMemorySize, ATT_SMEM_BYTES);
    cudaFuncSetAttribute(gemm_tc_kernel<0>,
                         cudaFuncAttributeMaxDynamicSharedMemorySize, GEMM_SMEM_BYTES);
    cudaFuncSetAttribute(gemm_tc_kernel<1>,
                         cudaFuncAttributeMaxDynamicSharedMemorySize, GEMM_SMEM_BYTES);
    cudaFuncSetAttribute(gemm_tc_kernel<2>,
                         cudaFuncAttributeMaxDynamicSharedMemorySize, GEMM_SMEM_BYTES);
    cudaFuncSetAttribute(gemm_tc_kernel<3>,
                         cudaFuncAttributeMaxDynamicSharedMemorySize, GEMM_SMEM_BYTES);

    // packs (deterministic, once per call)
    pack_qkv_w<<<(NL * ND * QLD + 255) / 256, 256>>>(wq, wk, wv, WQKV);
    pack_qkv_b<<<(NL * QLD + 255) / 256, 256>>>(bq, bk, bv, BQKV);
    pack_pool_w<<<576, 256>>>(pw1, PW);

    embed_kernel<<<NBS, ND>>>(te, pe, ids, X);

    for (int l = 0; l < NL; l++) {
        const size_t wOff = (size_t)l * ND * ND;
        const size_t dOff = (size_t)l * ND;
        ln_kernel<<<NBS, 128>>>(X, HB, g1 + dOff, b1 + dOff);
        run_big_gemm(HB, WQKV + (size_t)l * ND * QLD, BQKV + (size_t)l * QLD, nullptr,
                     QKV, NBS, QLD, ND, 0);
        attn_tc_kernel<<<dim3(NS / 128, NH, NB), 256, ATT_SMEM_BYTES>>>(
            QKV, QKV + ND, QKV + 2 * ND, rel + (size_t)l * (2 * NML - 1) * NDK, ids, AB);
        run_big_gemm(AB, wo + wOff, bo + dOff, X, X, NBS, ND, ND, 2);
        ln_kernel<<<NBS, 128>>>(X, HB, g2 + dOff, b2 + dOff);
        run_big_gemm(HB, fw1 + (size_t)l * ND * NFF, fb1 + (size_t)l * NFF, nullptr, FB,
                     NBS, NFF, ND, 1);
        run_big_gemm(FB, fw2 + (size_t)l * NFF * ND, fb2 + dOff, X, X, NBS, ND, NFF, 2);
    }

    ln_kernel<<<NBS, 128>>>(X, HB, fg, fbn);

    run_big_gemm(HB, PW, pb1, nullptr, PT, NBS, 384, 384, 3);
    pool_score_kernel<<<(4 * NBS + 3) / 4, 128>>>(PT, pw2, pb2, PS);
    pool_kernel<<<dim3(4, NB), 256>>>(HB, PS, ids, PD);

    run_small_gemm(PD, cw1, cb1, C1, NB, ND, 4 * ND, 1);
    run_small_gemm(C1, cw2, cb2, C2, NB, 192, ND, 1);
    run_small_gemm(C2, cw3, cb3, (float*)d_out, NB, NNC, 192, 0);
}

// round 13
// speedup vs baseline: 1.0641x; 1.0117x over previous
#include <cuda_runtime.h>
#include <math.h>
#include <stdint.h>

// ---------------- problem dims ----------------
#define NB   16
#define NS   768
#define ND   384
#define NH   12
#define NDK  32
#define NFF  1024
#define NL   6
#define NML  768
#define NNC  10
#define NBS  (NB*NS)          // 12288 rows
#define QLD  1152             // fused QKV row stride

// ---------------- scratch ----------------
#define OFF_X    ((size_t)0)
#define OFF_H    (OFF_X   + (size_t)NBS*ND)
#define OFF_QKV  (OFF_H   + (size_t)NBS*ND)
#define OFF_A    (OFF_QKV + (size_t)NBS*QLD)
#define OFF_FF   (OFF_A   + (size_t)NBS*ND)
#define OFF_PT   (OFF_FF  + (size_t)NBS*NFF)
#define OFF_PS   (OFF_PT  + (size_t)NBS*384)
#define OFF_PD   (OFF_PS  + (size_t)4*NBS)
#define OFF_C1   (OFF_PD  + (size_t)NB*4*ND)
#define OFF_C2   (OFF_C1  + (size_t)NB*ND)
#define OFF_PW   (OFF_C2  + (size_t)NB*192)
#define OFF_WQKV (OFF_PW  + (size_t)384*384)
#define OFF_BQKV (OFF_WQKV + (size_t)NL*ND*QLD)
#define SCRATCH_TOTAL (OFF_BQKV + (size_t)NL*QLD)

static __device__ float g_scratch[SCRATCH_TOTAL];

// ---------------- tf32 helpers ----------------
__device__ __forceinline__ float f2tf(float f) {
    uint32_t u;
    asm("cvt.rna.tf32.f32 %0, %1;" : "=r"(u) : "f"(f));
    return __uint_as_float(u);
}

__device__ __forceinline__ void mma_tf32(float* c, const float* a, const float* b) {
    asm volatile(
        "mma.sync.aligned.m16n8k8.row.col.f32.tf32.tf32.f32 "
        "{%0,%1,%2,%3}, {%4,%5,%6,%7}, {%8,%9}, {%0,%1,%2,%3};"
        : "+f"(c[0]), "+f"(c[1]), "+f"(c[2]), "+f"(c[3])
        : "r"(__float_as_uint(a[0])), "r"(__float_as_uint(a[1])),
          "r"(__float_as_uint(a[2])), "r"(__float_as_uint(a[3])),
          "r"(__float_as_uint(b[0])), "r"(__float_as_uint(b[1])));
}

// ---------------- embed (float4) ----------------
__global__ void embed_kernel(const float* __restrict__ te, const float* __restrict__ pe,
                             const int* __restrict__ ids, float* __restrict__ x) {
    int row = blockIdx.x;
    int s   = row % NS;
    int id  = ids[row];
    const float4* tp = (const float4*)(te + (size_t)id * ND);
    const float4* pp = (const float4*)(pe + (size_t)s * ND);
    float4* xp = (float4*)(x + (size_t)row * ND);
    for (int i = threadIdx.x; i < 96; i += 128) {
        float4 a = tp[i], b = pp[i];
        xp[i] = make_float4(a.x + b.x, a.y + b.y, a.z + b.z, a.w + b.w);
    }
}

// ---------------- weight packers ----------------
__global__ void pack_pool_w(const float* __restrict__ pw1, float* __restrict__ Wp) {
    int idx = blockIdx.x * 256 + threadIdx.x;
    if (idx < 384 * 384) {
        int k = idx / 384, c = idx % 384;
        int h = c / 96, j = c % 96;
        Wp[idx] = pw1[((size_t)h * 384 + k) * 96 + j];
    }
}

__global__ void pack_qkv_w(const float* __restrict__ wq, const float* __restrict__ wk,
                           const float* __restrict__ wv, float* __restrict__ Wf) {
    int idx = blockIdx.x * 256 + threadIdx.x;
    if (idx >= NL * ND * QLD) return;
    int l   = idx / (ND * QLD);
    int rem = idx - l * (ND * QLD);
    int k   = rem / QLD;
    int c   = rem - k * QLD;
    int sel = c / ND;
    int col = c - sel * ND;
    const float* src = (sel == 0) ? wq : (sel == 1) ? wk : wv;
    Wf[idx] = src[((size_t)l * ND + k) * ND + col];
}

__global__ void pack_qkv_b(const float* __restrict__ bq, const float* __restrict__ bk,
                           const float* __restrict__ bv, float* __restrict__ Bf) {
    int idx = blockIdx.x * 256 + threadIdx.x;
    if (idx >= NL * QLD) return;
    int l = idx / QLD;
    int c = idx - l * QLD;
    int sel = c / ND;
    int col = c - sel * ND;
    const float* src = (sel == 0) ? bq : (sel == 1) ? bk : bv;
    Bf[idx] = src[l * ND + col];
}

// ---------------- layernorm: warp per row, 8 rows per block ----------------
__global__ void ln_kernel(const float* __restrict__ in, float* __restrict__ out,
                          const float* __restrict__ g, const float* __restrict__ b) {
    int row  = blockIdx.x * 8 + (threadIdx.x >> 5);
    int lane = threadIdx.x & 31;
    const float4* p = (const float4*)(in + (size_t)row * ND);
    float4 v[3];
    float s = 0.f;
    #pragma unroll
    for (int i = 0; i < 3; i++) {
        v[i] = p[lane + i * 32];
        s += v[i].x + v[i].y + v[i].z + v[i].w;
    }
    #pragma unroll
    for (int o = 16; o > 0; o >>= 1) s += __shfl_xor_sync(0xffffffffu, s, o);
    float mean = s * (1.f / ND);
    float vs = 0.f;
    #pragma unroll
    for (int i = 0; i < 3; i++) {
        float a0 = v[i].x - mean, a1 = v[i].y - mean;
        float a2 = v[i].z - mean, a3 = v[i].w - mean;
        vs += a0 * a0 + a1 * a1 + a2 * a2 + a3 * a3;
    }
    #pragma unroll
    for (int o = 16; o > 0; o >>= 1) vs += __shfl_xor_sync(0xffffffffu, vs, o);
    float inv = rsqrtf(vs * (1.f / ND) + 1e-5f);
    float4* o4 = (float4*)(out + (size_t)row * ND);
    #pragma unroll
    for (int i = 0; i < 3; i++) {
        float4 gv = ((const float4*)g)[lane + i * 32];
        float4 bv = ((const float4*)b)[lane + i * 32];
        float4 o;
        o.x = (v[i].x - mean) * inv * gv.x + bv.x;
        o.y = (v[i].y - mean) * inv * gv.y + bv.y;
        o.z = (v[i].z - mean) * inv * gv.z + bv.z;
        o.w = (v[i].w - mean) * inv * gv.w + bv.w;
        o4[lane + i * 32] = o;
    }
}

// ================= tf32 TC GEMM: 256x128 tile, BK=16, 256 threads (R8 config) =================
#define GSTRIDE 136
#define GEMM_SMEM_WORDS (2*4096 + 2*16*GSTRIDE)
#define GEMM_SMEM_BYTES (GEMM_SMEM_WORDS * 4)

template<int EPI>
__global__ void __launch_bounds__(256, 1)
gemm_tc_kernel(const float* __restrict__ A, const float* __restrict__ W,
               const float* __restrict__ bias, const float* __restrict__ res,
               float* __restrict__ C, int M, int N, int K) {
    extern __shared__ __align__(16) float dsm[];
    float* As2 = dsm;                       // [2][4096]
    float* Bsf = dsm + 8192;                // [2][16][GSTRIDE]

    const int t    = threadIdx.x;
    const int lane = t & 31;
    const int warp = t >> 5;
    const int wn   = (warp & 1) * 64;
    const int gid  = lane >> 2;
    const int tig  = lane & 3;
    const int brow = blockIdx.y * 256;
    const int bcol = blockIdx.x * 128;

    const int ar  = t;
    const int asw = ((ar & 7) >> 1) & 3;
    const int amb = (ar >> 4) * 128 + (ar & 7) * 16 + ((ar >> 3) & 1);
    const int bkr = t >> 5;
    const int bc  = lane * 4;

    const int afrag = (warp >> 1) * 512 + gid * 16 + ((tig ^ ((gid >> 1) & 3)) << 2);

    const float* Ap = A + (size_t)(brow + ar) * K;

    float acc[4][8][4];
    #pragma unroll
    for (int i = 0; i < 4; i++)
        #pragma unroll
        for (int j = 0; j < 8; j++)
            #pragma unroll
            for (int r = 0; r < 4; r++) acc[i][j][r] = 0.f;

    const int ntiles = K / 16;

    {
        #pragma unroll
        for (int q = 0; q < 4; q++) {
            float4 aq = *(const float4*)&Ap[q * 4];
            const float* ae = &aq.x;
            int base = (q >> 1) * 2048 + amb + (q & 1) * 2;
            #pragma unroll
            for (int j = 0; j < 4; j++)
                As2[base + ((j ^ asw) << 2)] = f2tf(ae[j]);
        }
        float4 b0 = *(const float4*)&W[(size_t)bkr * N + bcol + bc];
        float4 b1 = *(const float4*)&W[(size_t)(bkr + 8) * N + bcol + bc];
        float4 c0, c1;
        c0.x = f2tf(b0.x); c0.y = f2tf(b0.y); c0.z = f2tf(b0.z); c0.w = f2tf(b0.w);
        c1.x = f2tf(b1.x); c1.y = f2tf(b1.y); c1.z = f2tf(b1.z); c1.w = f2tf(b1.w);
        *(float4*)&Bsf[bkr * GSTRIDE + bc]       = c0;
        *(float4*)&Bsf[(bkr + 8) * GSTRIDE + bc] = c1;
    }
    __syncthreads();

    for (int tt = 0; tt < ntiles; tt++) {
        const int cur = tt & 1;
        const int nxt = cur ^ 1;
        const bool more = (tt + 1 < ntiles);
        float4 apre[4], b0, b1;
        if (more) {
            const int k0 = (tt + 1) * 16;
            #pragma unroll
            for (int q = 0; q < 4; q++) apre[q] = *(const float4*)&Ap[k0 + q * 4];
            b0 = *(const float4*)&W[(size_t)(k0 + bkr) * N + bcol + bc];
            b1 = *(const float4*)&W[(size_t)(k0 + bkr + 8) * N + bcol + bc];
        }
        const float* Ab = As2 + cur * 4096;
        const float* Bb = Bsf + cur * (16 * GSTRIDE);
        #pragma unroll
        for (int ks = 0; ks < 2; ks++) {
            float a[4][4], b[8][2];
            #pragma unroll
            for (int mt = 0; mt < 4; mt++) {
                float4 av = *(const float4*)&Ab[ks * 2048 + mt * 128 + afrag];
                a[mt][0] = av.x; a[mt][1] = av.y; a[mt][2] = av.z; a[mt][3] = av.w;
            }
            #pragma unroll
            for (int nt = 0; nt < 8; nt++) {
                const int n0 = wn + nt * 8 + gid;
                b[nt][0] = Bb[(ks * 8 + tig) * GSTRIDE + n0];
                b[nt][1] = Bb[(ks * 8 + tig + 4) * GSTRIDE + n0];
            }
            #pragma unroll
            for (int mt = 0; mt < 4; mt++)
                #pragma unroll
                for (int nt = 0; nt < 8; nt++)
                    mma_tf32(acc[mt][nt], a[mt], b[nt]);
        }
        if (more) {
            float* An = As2 + nxt * 4096;
            #pragma unroll
            for (int q = 0; q < 4; q++) {
                const float* ae = &apre[q].x;
                int base = (q >> 1) * 2048 + amb + (q & 1) * 2;
                #pragma unroll
                for (int j = 0; j < 4; j++)
                    An[base + ((j ^ asw) << 2)] = f2tf(ae[j]);
            }
            float4 c0, c1;
            c0.x = f2tf(b0.x); c0.y = f2tf(b0.y); c0.z = f2tf(b0.z); c0.w = f2tf(b0.w);
            c1.x = f2tf(b1.x); c1.y = f2tf(b1.y); c1.z = f2tf(b1.z); c1.w = f2tf(b1.w);
            float* Bn = Bsf + nxt * (16 * GSTRIDE);
            *(float4*)&Bn[bkr * GSTRIDE + bc]       = c0;
            *(float4*)&Bn[(bkr + 8) * GSTRIDE + bc] = c1;
        }
        __syncthreads();
    }

    const int wm = (warp >> 1) * 64;
    #pragma unroll
    for (int mt = 0; mt < 4; mt++) {
        const int r0 = brow + wm + mt * 16 + gid;
        #pragma unroll
        for (int nt = 0; nt < 8; nt++) {
            const int c0 = bcol + wn + nt * 8 + tig * 2;
            float bx = bias[c0], by = bias[c0 + 1];
            float v00 = acc[mt][nt][0] + bx;
            float v01 = acc[mt][nt][1] + by;
            float v10 = acc[mt][nt][2] + bx;
            float v11 = acc[mt][nt][3] + by;
            if (EPI == 1) {
                v00 = 0.5f * v00 * (1.f + erff(v00 * 0.70710678118654752f));
                v01 = 0.5f * v01 * (1.f + erff(v01 * 0.70710678118654752f));
                v10 = 0.5f * v10 * (1.f + erff(v10 * 0.70710678118654752f));
                v11 = 0.5f * v11 * (1.f + erff(v11 * 0.70710678118654752f));
            } else if (EPI == 2) {
                float2 r0v = *(const float2*)&res[(size_t)r0 * N + c0];
                float2 r1v = *(const float2*)&res[(size_t)(r0 + 8) * N + c0];
                v00 += r0v.x; v01 += r0v.y; v10 += r1v.x; v11 += r1v.y;
            } else if (EPI == 3) {
                v00 = tanhf(v00); v01 = tanhf(v01);
                v10 = tanhf(v10); v11 = tanhf(v11);
            }
            *(float2*)&C[(size_t)r0 * N + c0]       = make_float2(v00, v01);
            *(float2*)&C[(size_t)(r0 + 8) * N + c0] = make_float2(v10, v11);
        }
    }
}

// ---------------- small guarded SGEMM (classifier) ----------------
template<int EPI>
__global__ void gemm_kernel(const float* __restrict__ A, const float* __restrict__ W,
                            const float* __restrict__ bias,
                            float* __restrict__ C, int M, int N, int K) {
    __shared__ float As[16][65];
    __shared__ float Bs[16][64];
    const int brow = blockIdx.y * 64;
    const int bcol = blockIdx.x * 64;
    const int t  = threadIdx.x;
    const int ty = t >> 4, tx = t & 15;
    float acc[4][4] = {};
    for (int k0 = 0; k0 < K; k0 += 16) {
        #pragma unroll
        for (int l = t; l < 1024; l += 256) {
            int r = l >> 4, kk = l & 15;
            int gr = brow + r;
            As[kk][r] = (gr < M && k0 + kk < K) ? A[(size_t)gr * K + k0 + kk] : 0.f;
        }
        #pragma unroll
        for (int l = t; l < 1024; l += 256) {
            int kk = l >> 6, c = l & 63;
            int gc = bcol + c;
            Bs[kk][c] = (gc < N && k0 + kk < K) ? W[(size_t)(k0 + kk) * N + gc] : 0.f;
        }
        __syncthreads();
        #pragma unroll
        for (int kk = 0; kk < 16; kk++) {
            float a[4], bvals[4];
            #pragma unroll
            for (int i = 0; i < 4; i++) a[i] = As[kk][ty * 4 + i];
            #pragma unroll
            for (int j = 0; j < 4; j++) bvals[j] = Bs[kk][tx * 4 + j];
            #pragma unroll
            for (int i = 0; i < 4; i++)
                #pragma unroll
                for (int j = 0; j < 4; j++)
                    acc[i][j] += a[i] * bvals[j];
        }
        __syncthreads();
    }
    #pragma unroll
    for (int i = 0; i < 4; i++) {
        int row = brow + ty * 4 + i;
        if (row >= M) continue;
        #pragma unroll
        for (int j = 0; j < 4; j++) {
            int col = bcol + tx * 4 + j;
            if (col >= N) continue;
            float v = acc[i][j] + bias[col];
            if (EPI == 1) v = 0.5f * v * (1.f + erff(v * 0.70710678118654752f));
            else if (EPI == 3) v = tanhf(v);
            C[(size_t)row * N + col] = v;
        }
    }
}

// ================= tensor-core flash attention with banded rel bias =================
// 2 CTAs/SM target: rel MMA split into two 5-tile halves to cap live registers.
#define ATT_SMEM_WORDS 25920
#define ATT_SMEM_BYTES (ATT_SMEM_WORDS * 4)

__global__ void __launch_bounds__(256, 2)
attn_tc_kernel(const float* __restrict__ q, const float* __restrict__ k,
               const float* __restrict__ v, const float* __restrict__ rel,
               const int* __restrict__ ids, float* __restrict__ out) {
    extern __shared__ float sm[];
    float* Qs = sm;                   // [32][132]
    float* Ks = sm + 4224;            // [32][68]
    float* Rs = sm + 6400;            // [32][200]
    float* Vs = sm + 12800;           // [64][36]
    float* WS = sm + 15104;           // [8][16][84]
    int*   Mk = (int*)(sm + 25856);   // [64]

    const int q0 = blockIdx.x * 128;
    const int h  = blockIdx.y;
    const int b  = blockIdx.z;
    const int t    = threadIdx.x;
    const int lane = t & 31;
    const int w    = t >> 5;
    const int gid  = lane >> 2;
    const int tig  = lane & 3;
    float* WSw = WS + w * (16 * 84);
    const int j0w = 112 - 16 * w;
    const float scale = 0.17677669529663689f;

    {
        const float* qb = q + ((size_t)(b * NS + q0)) * QLD + h * NDK;
        #pragma unroll
        for (int i = t; i < 1024; i += 256) {
            int r = i >> 3, d0 = (i & 7) * 4;
            float4 x = *(const float4*)&qb[(size_t)r * QLD + d0];
            Qs[(d0 + 0) * 132 + r] = f2tf(x.x);
            Qs[(d0 + 1) * 132 + r] = f2tf(x.y);
            Qs[(d0 + 2) * 132 + r] = f2tf(x.z);
            Qs[(d0 + 3) * 132 + r] = f2tf(x.w);
        }
    }
    __syncthreads();

    float af[4][4];
    #pragma unroll
    for (int ks = 0; ks < 4; ks++) {
        int kk = ks * 8 + tig;
        int m0 = w * 16 + gid;
        af[ks][0] = Qs[kk * 132 + m0];
        af[ks][1] = Qs[kk * 132 + m0 + 8];
        af[ks][2] = Qs[(kk + 4) * 132 + m0];
        af[ks][3] = Qs[(kk + 4) * 132 + m0 + 8];
    }

    float m_lo = -INFINITY, m_hi = -INFINITY, l_lo = 0.f, l_hi = 0.f;
    float oa[4][4];
    #pragma unroll
    for (int i = 0; i < 4; i++)
        #pragma unroll
        for (int j = 0; j < 4; j++) oa[i][j] = 0.f;

    for (int k0 = 0; k0 < NS; k0 += 64) {
        __syncthreads();
        {
            const float* kb = k + ((size_t)(b * NS + k0)) * QLD + h * NDK;
            const float* vb = v + ((size_t)(b * NS + k0)) * QLD + h * NDK;
            #pragma unroll
            for (int i = t; i < 512; i += 256) {
                int r = i >> 3, d0 = (i & 7) * 4;
                float4 x = *(const float4*)&kb[(size_t)r * QLD + d0];
                Ks[(d0 + 0) * 68 + r] = f2tf(x.x);
                Ks[(d0 + 1) * 68 + r] = f2tf(x.y);
                Ks[(d0 + 2) * 68 + r] = f2tf(x.z);
                Ks[(d0 + 3) * 68 + r] = f2tf(x.w);
                float4 y = *(const float4*)&vb[(size_t)r * QLD + d0];
                float4 z;
                z.x = f2tf(y.x); z.y = f2tf(y.y); z.z = f2tf(y.z); z.w = f2tf(y.w);
                *(float4*)&Vs[r * 36 + d0] = z;
            }
            const float* rb = rel + (size_t)(k0 - q0 + 640) * NDK;
            for (int i = t; i < 191 * 8; i += 256) {
                int j = i >> 3, d0 = (i & 7) * 4;
                float4 x = *(const float4*)&rb[(size_t)j * NDK + d0];
                Rs[(d0 + 0) * 200 + j] = f2tf(x.x);
                Rs[(d0 + 1) * 200 + j] = f2tf(x.y);
                Rs[(d0 + 2) * 200 + j] = f2tf(x.z);
                Rs[(d0 + 3) * 200 + j] = f2tf(x.w);
            }
            if (t < 64) Mk[t] = ids[b * NS + k0 + t];
        }
        __syncthreads();

        // ---- rel-band MMA: P[16 x 80], two 5-tile halves (register pressure) ----
        #pragma unroll
        for (int half = 0; half < 2; half++) {
            float rc[5][4];
            #pragma unroll
            for (int nt = 0; nt < 5; nt++)
                #pragma unroll
                for (int e = 0; e < 4; e++) rc[nt][e] = 0.f;
            #pragma unroll
            for (int ks = 0; ks < 4; ks++) {
                int kk = ks * 8 + tig;
                #pragma unroll
                for (int nt = 0; nt < 5; nt++) {
                    int col = j0w + (half * 5 + nt) * 8 + gid;
                    float bb[2];
                    bb[0] = Rs[kk * 200 + col];
                    bb[1] = Rs[(kk + 4) * 200 + col];
                    mma_tf32(rc[nt], af[ks], bb);
                }
            }
            #pragma unroll
            for (int nt = 0; nt < 5; nt++) {
                int c0 = (half * 5 + nt) * 8 + 2 * tig;
                WSw[gid * 84 + c0]           = rc[nt][0];
                WSw[gid * 84 + c0 + 1]       = rc[nt][1];
                WSw[(gid + 8) * 84 + c0]     = rc[nt][2];
                WSw[(gid + 8) * 84 + c0 + 1] = rc[nt][3];
            }
        }
        __syncwarp();

        // ---- QK MMA: S1[16 x 64] ----
        float qa[8][4];
        #pragma unroll
        for (int nt = 0; nt < 8; nt++)
            #pragma unroll
            for (int e = 0; e < 4; e++) qa[nt][e] = 0.f;
        #pragma unroll
        for (int ks = 0; ks < 4; ks++) {
            int kk = ks * 8 + tig;
            #pragma unroll
            for (int nt = 0; nt < 8; nt++) {
                int col = nt * 8 + gid;
                float bb[2];
                bb[0] = Ks[kk * 68 + col];
                bb[1] = Ks[(kk + 4) * 68 + col];
                mma_tf32(qa[nt], af[ks], bb);
            }
        }

        // ---- combine + mask ----
        #pragma unroll
        for (int nt = 0; nt < 8; nt++) {
            int kl0 = nt * 8 + 2 * tig;
            int kl1 = kl0 + 1;
            int rlo = gid, rhi = gid + 8;
            bool m0b = (Mk[kl0] == 0), m1b = (Mk[kl1] == 0);
            qa[nt][0] = m0b ? -INFINITY : (qa[nt][0] + WSw[rlo * 84 + kl0 + 15 - rlo]) * scale;
            qa[nt][1] = m1b ? -INFINITY : (qa[nt][1] + WSw[rlo * 84 + kl1 + 15 - rlo]) * scale;
            qa[nt][2] = m0b ? -INFINITY : (qa[nt][2] + WSw[rhi * 84 + kl0 + 15 - rhi]) * scale;
            qa[nt][3] = m1b ? -INFINITY : (qa[nt][3] + WSw[rhi * 84 + kl1 + 15 - rhi]) * scale;
        }
        __syncwarp();

        // ---- online softmax ----
        float tm_lo = -INFINITY, tm_hi = -INFINITY;
        #pragma unroll
        for (int nt = 0; nt < 8; nt++) {
            tm_lo = fmaxf(tm_lo, fmaxf(qa[nt][0], qa[nt][1]));
            tm_hi = fmaxf(tm_hi, fmaxf(qa[nt][2], qa[nt][3]));
        }
        tm_lo = fmaxf(tm_lo, __shfl_xor_sync(0xffffffffu, tm_lo, 1));
        tm_lo = fmaxf(tm_lo, __shfl_xor_sync(0xffffffffu, tm_lo, 2));
        tm_hi = fmaxf(tm_hi, __shfl_xor_sync(0xffffffffu, tm_hi, 1));
        tm_hi = fmaxf(tm_hi, __shfl_xor_sync(0xffffffffu, tm_hi, 2));

        float nm_lo = fmaxf(m_lo, tm_lo);
        float nm_hi = fmaxf(m_hi, tm_hi);
        float c_lo = 1.f, c_hi = 1.f, sum_lo = 0.f, sum_hi = 0.f;

        if (nm_lo == -INFINITY) {
            #pragma unroll
            for (int nt = 0; nt < 8; nt++) {
                int c0 = nt * 8 + 2 * tig;
                WSw[gid * 84 + c0] = 0.f; WSw[gid * 84 + c0 + 1] = 0.f;
            }
        } else {
            c_lo = __expf(m_lo - nm_lo);
            #pragma unroll
            for (int nt = 0; nt < 8; nt++) {
                int c0 = nt * 8 + 2 * tig;
                float p0 = __expf(qa[nt][0] - nm_lo);
                float p1 = __expf(qa[nt][1] - nm_lo);
                sum_lo += p0 + p1;
                WSw[gid * 84 + c0]     = f2tf(p0);
                WSw[gid * 84 + c0 + 1] = f2tf(p1);
            }
        }
        if (nm_hi == -INFINITY) {
            #pragma unroll
            for (int nt = 0; nt < 8; nt++) {
                int c0 = nt * 8 + 2 * tig;
                WSw[(gid + 8) * 84 + c0] = 0.f; WSw[(gid + 8) * 84 + c0 + 1] = 0.f;
            }
        } else {
            c_hi = __expf(m_hi - nm_hi);
            #pragma unroll
            for (int nt = 0; nt < 8; nt++) {
                int c0 = nt * 8 + 2 * tig;
                float p0 = __expf(qa[nt][2] - nm_hi);
                float p1 = __expf(qa[nt][3] - nm_hi);
                sum_hi += p0 + p1;
                WSw[(gid + 8) * 84 + c0]     = f2tf(p0);
                WSw[(gid + 8) * 84 + c0 + 1] = f2tf(p1);
            }
        }
        sum_lo += __shfl_xor_sync(0xffffffffu, sum_lo, 1);
        sum_lo += __shfl_xor_sync(0xffffffffu, sum_lo, 2);
        sum_hi += __shfl_xor_sync(0xffffffffu, sum_hi, 1);
        sum_hi += __shfl_xor_sync(0xffffffffu, sum_hi, 2);
        m_lo = nm_lo; m_hi = nm_hi;
        l_lo = l_lo * c_lo + sum_lo;
        l_hi = l_hi * c_hi + sum_hi;
        #pragma unroll
        for (int nt = 0; nt < 4; nt++) {
            oa[nt][0] *= c_lo; oa[nt][1] *= c_lo;
            oa[nt][2] *= c_hi; oa[nt][3] *= c_hi;
        }
        __syncwarp();

        // ---- PV MMA ----
        #pragma unroll
        for (int ks = 0; ks < 8; ks++) {
            int kk = ks * 8 + tig;
            float pa[4];
            pa[0] = WSw[gid * 84 + kk];
            pa[1] = WSw[(gid + 8) * 84 + kk];
            pa[2] = WSw[gid * 84 + kk + 4];
            pa[3] = WSw[(gid + 8) * 84 + kk + 4];
            #pragma unroll
            for (int nt = 0; nt < 4; nt++) {
                int col = nt * 8 + gid;
                float bb[2];
                bb[0] = Vs[kk * 36 + col];
                bb[1] = Vs[(kk + 4) * 36 + col];
                mma_tf32(oa[nt], pa, bb);
            }
        }
    }

    float inv_lo = (l_lo > 0.f) ? 1.f / l_lo : 0.f;
    float inv_hi = (l_hi > 0.f) ? 1.f / l_hi : 0.f;
    const int rlo = b * NS + q0 + w * 16 + gid;
    #pragma unroll
    for (int nt = 0; nt < 4; nt++) {
        int col = h * NDK + nt * 8 + 2 * tig;
        out[(size_t)rlo * ND + col]           = oa[nt][0] * inv_lo;
        out[(size_t)rlo * ND + col + 1]       = oa[nt][1] * inv_lo;
        out[(size_t)(rlo + 8) * ND + col]     = oa[nt][2] * inv_hi;
        out[(size_t)(rlo + 8) * ND + col + 1] = oa[nt][3] * inv_hi;
    }
}

// ---------------- pooling ----------------
__global__ void pool_score_kernel(const float* __restrict__ tmp, const float* __restrict__ pw2,
                                  const float* __restrict__ pb2, float* __restrict__ scores) {
    int gid = blockIdx.x * (blockDim.x >> 5) + (threadIdx.x >> 5);
    if (gid >= 4 * NBS) return;
    int head = gid / NBS;
    int row  = gid - head * NBS;
    int lane = threadIdx.x & 31;
    const float* p = tmp + (size_t)row * 384 + head * 96;
    float s = 0.f;
    for (int j = lane; j < 96; j += 32) s += p[j] * pw2[head * 96 + j];
    #pragma unroll
    for (int o = 16; o > 0; o >>= 1) s += __shfl_xor_sync(0xffffffffu, s, o);
    if (lane == 0) scores[gid] = s + pb2[head];
}

__global__ void pool_kernel(const float* __restrict__ x, const float* __restrict__ scores,
                            const int* __restrict__ ids, float* __restrict__ pooled) {
    const int head = blockIdx.x;
    const int b    = blockIdx.y;
    __shared__ float ps[NS];
    __shared__ float red[8];
    const float* sc = scores + (size_t)head * NBS + (size_t)b * NS;

    float m = -INFINITY;
    for (int s = threadIdx.x; s < NS; s += 256) {
        float val = (ids[b * NS + s] == 0) ? -INFINITY : sc[s];
        ps[s] = val;
        m = fmaxf(m, val);
    }
    #pragma unroll
    for (int o = 16; o > 0; o >>= 1) m = fmaxf(m, __shfl_xor_sync(0xffffffffu, m, o));
    if ((threadIdx.x & 31) == 0) red[threadIdx.x >> 5] = m;
    __syncthreads();
    float M = -INFINITY;
    #pragma unroll
    for (int i = 0; i < 8; i++) M = fmaxf(M, red[i]);
    __syncthreads();

    float sum = 0.f;
    for (int s = threadIdx.x; s < NS; s += 256) {
        float p = __expf(ps[s] - M);
        ps[s] = p;
        sum += p;
    }
    #pragma unroll
    for (int o = 16; o > 0; o >>= 1) sum += __shfl_xor_sync(0xffffffffu, sum, o);
    if ((threadIdx.x & 31) == 0) red[threadIdx.x >> 5] = sum;
    __syncthreads();
    float T = 0.f;
    #pragma unroll
    for (int i = 0; i < 8; i++) T += red[i];
    __syncthreads();
    float inv = 1.f / T;

    for (int d = threadIdx.x; d < ND; d += 256) {
        float acc = 0.f;
        const float* xp = x + (size_t)b * NS * ND + d;
        for (int s = 0; s < NS; s++) acc += ps[s] * xp[(size_t)s * ND];
        pooled[(size_t)b * (4 * ND) + head * ND + d] = acc * inv;
    }
}

// ---------------- dispatchers ----------------
static void run_big_gemm(const float* A, const float* W, const float* bias, const float* res,
                         float* C, int M, int N, int K, int epi) {
    dim3 grid(N / 128, M / 256);
    switch (epi) {
        case 0: gemm_tc_kernel<0><<<grid, 256, GEMM_SMEM_BYTES>>>(A, W, bias, res, C, M, N, K); break;
        case 1: gemm_tc_kernel<1><<<grid, 256, GEMM_SMEM_BYTES>>>(A, W, bias, res, C, M, N, K); break;
        case 2: gemm_tc_kernel<2><<<grid, 256, GEMM_SMEM_BYTES>>>(A, W, bias, res, C, M, N, K); break;
        case 3: gemm_tc_kernel<3><<<grid, 256, GEMM_SMEM_BYTES>>>(A, W, bias, res, C, M, N, K); break;
    }
}

static void run_small_gemm(const float* A, const float* W, const float* bias,
                           float* C, int M, int N, int K, int epi) {
    dim3 grid((N + 63) / 64, (M + 63) / 64);
    switch (epi) {
        case 0: gemm_kernel<0><<<grid, 256>>>(A, W, bias, C, M, N, K); break;
        case 1: gemm_kernel<1><<<grid, 256>>>(A, W, bias, C, M, N, K); break;
        case 3: gemm_kernel<3><<<grid, 256>>>(A, W, bias, C, M, N, K); break;
    }
}

// ---------------- entry ----------------
extern "C" void kernel_launch(void* const* d_in, const int* in_sizes, int n_in,
                              void* d_out, int out_size) {
    const float* te   = (const float*)d_in[0];
    const float* pe   = (const float*)d_in[1];
    const float* wq   = (const float*)d_in[2];
    const float* bq   = (const float*)d_in[3];
    const float* wk   = (const float*)d_in[4];
    const float* bk   = (const float*)d_in[5];
    const float* wv   = (const float*)d_in[6];
    const float* bv   = (const float*)d_in[7];
    const float* wo   = (const float*)d_in[8];
    const float* bo   = (const float*)d_in[9];
    const float* rel  = (const float*)d_in[10];
    const float* g1   = (const float*)d_in[11];
    const float* b1   = (const float*)d_in[12];
    const float* g2   = (const float*)d_in[13];
    const float* b2   = (const float*)d_in[14];
    const float* fw1  = (const float*)d_in[15];
    const float* fb1  = (const float*)d_in[16];
    const float* fw2  = (const float*)d_in[17];
    const float* fb2  = (const float*)d_in[18];
    const float* fg   = (const float*)d_in[19];
    const float* fbn  = (const float*)d_in[20];
    const float* pw1  = (const float*)d_in[21];
    const float* pb1  = (const float*)d_in[22];
    const float* pw2  = (const float*)d_in[23];
    const float* pb2  = (const float*)d_in[24];
    const float* cw1  = (const float*)d_in[25];
    const float* cb1  = (const float*)d_in[26];
    const float* cw2  = (const float*)d_in[27];
    const float* cb2  = (const float*)d_in[28];
    const float* cw3  = (const float*)d_in[29];
    const float* cb3  = (const float*)d_in[30];
    const int*   ids  = (const int*)d_in[31];

    float* S;
    cudaGetSymbolAddress((void**)&S, g_scratch);
    float* X    = S + OFF_X;
    float* HB   = S + OFF_H;
    float* QKV  = S + OFF_QKV;
    float* AB   = S + OFF_A;
    float* FB   = S + OFF_FF;
    float* PT   = S + OFF_PT;
    float* PS   = S + OFF_PS;
    float* PD   = S + OFF_PD;
    float* C1   = S + OFF_C1;
    float* C2   = S + OFF_C2;
    float* PW   = S + OFF_PW;
    float* WQKV = S + OFF_WQKV;
    float* BQKV = S + OFF_BQKV;

    cudaFuncSetAttribute(attn_tc_kernel,
                         cudaFuncAttributeMaxDynamicSharedMemorySize, ATT_SMEM_BYTES);
    cudaFuncSetAttribute(gemm_tc_kernel<0>,
                         cudaFuncAttributeMaxDynamicSharedMemorySize, GEMM_SMEM_BYTES);
    cudaFuncSetAttribute(gemm_tc_kernel<1>,
                         cudaFuncAttributeMaxDynamicSharedMemorySize, GEMM_SMEM_BYTES);
    cudaFuncSetAttribute(gemm_tc_kernel<2>,
                         cudaFuncAttributeMaxDynamicSharedMemorySize, GEMM_SMEM_BYTES);
    cudaFuncSetAttribute(gemm_tc_kernel<3>,
                         cudaFuncAttributeMaxDynamicSharedMemorySize, GEMM_SMEM_BYTES);

    pack_qkv_w<<<(NL * ND * QLD + 255) / 256, 256>>>(wq, wk, wv, WQKV);
    pack_qkv_b<<<(NL * QLD + 255) / 256, 256>>>(bq, bk, bv, BQKV);
    pack_pool_w<<<576, 256>>>(pw1, PW);

    embed_kernel<<<NBS, 128>>>(te, pe, ids, X);

    for (int l = 0; l < NL; l++) {
        const size_t wOff = (size_t)l * ND * ND;
        const size_t dOff = (size_t)l * ND;
        ln_kernel<<<NBS / 8, 256>>>(X, HB, g1 + dOff, b1 + dOff);
        run_big_gemm(HB, WQKV + (size_t)l * ND * QLD, BQKV + (size_t)l * QLD, nullptr,
                     QKV, NBS, QLD, ND, 0);
        attn_tc_kernel<<<dim3(NS / 128, NH, NB), 256, ATT_SMEM_BYTES>>>(
            QKV, QKV + ND, QKV + 2 * ND, rel + (size_t)l * (2 * NML - 1) * NDK, ids, AB);
        run_big_gemm(AB, wo + wOff, bo + dOff, X, X, NBS, ND, ND, 2);
        ln_kernel<<<NBS / 8, 256>>>(X, HB, g2 + dOff, b2 + dOff);
        run_big_gemm(HB, fw1 + (size_t)l * ND * NFF, fb1 + (size_t)l * NFF, nullptr, FB,
                     NBS, NFF, ND, 1);
        run_big_gemm(FB, fw2 + (size_t)l * NFF * ND, fb2 + dOff, X, X, NBS, ND, NFF, 2);
    }

    ln_kernel<<<NBS / 8, 256>>>(X, HB, fg, fbn);

    run_big_gemm(HB, PW, pb1, nullptr, PT, NBS, 384, 384, 3);
    pool_score_kernel<<<(4 * NBS + 3) / 4, 128>>>(PT, pw2, pb2, PS);
    pool_kernel<<<dim3(4, NB), 256>>>(HB, PS, ids, PD);

    run_small_gemm(PD, cw1, cb1, C1, NB, ND, 4 * ND, 1);
    run_small_gemm(C1, cw2, cb2, C2, NB, 192, ND, 1);
    run_small_gemm(C2, cw3, cb3, (float*)d_out, NB, NNC, 192, 0);
}

// round 14
// speedup vs baseline: 1.1241x; 1.0564x over previous
#include <cuda_runtime.h>
#include <math.h>
#include <stdint.h>

// ---------------- problem dims ----------------
#define NB   16
#define NS   768
#define ND   384
#define NH   12
#define NDK  32
#define NFF  1024
#define NL   6
#define NML  768
#define NNC  10
#define NBS  (NB*NS)          // 12288 rows
#define QLD  1152             // fused QKV row stride

// ---------------- scratch ----------------
#define OFF_X    ((size_t)0)
#define OFF_H    (OFF_X   + (size_t)NBS*ND)
#define OFF_QKV  (OFF_H   + (size_t)NBS*ND)
#define OFF_A    (OFF_QKV + (size_t)NBS*QLD)
#define OFF_FF   (OFF_A   + (size_t)NBS*ND)
#define OFF_PT   (OFF_FF  + (size_t)NBS*NFF)
#define OFF_PS   (OFF_PT  + (size_t)NBS*384)
#define OFF_PD   (OFF_PS  + (size_t)4*NBS)
#define OFF_C1   (OFF_PD  + (size_t)NB*4*ND)
#define OFF_C2   (OFF_C1  + (size_t)NB*ND)
#define OFF_PW   (OFF_C2  + (size_t)NB*192)
#define OFF_WQKV (OFF_PW  + (size_t)384*384)
#define OFF_BQKV (OFF_WQKV + (size_t)NL*ND*QLD)
#define SCRATCH_TOTAL (OFF_BQKV + (size_t)NL*QLD)

static __device__ float g_scratch[SCRATCH_TOTAL];

// ---------------- tf32 helpers ----------------
__device__ __forceinline__ float f2tf(float f) {
    uint32_t u;
    asm("cvt.rna.tf32.f32 %0, %1;" : "=r"(u) : "f"(f));
    return __uint_as_float(u);
}

__device__ __forceinline__ void mma_tf32(float* c, const float* a, const float* b) {
    asm volatile(
        "mma.sync.aligned.m16n8k8.row.col.f32.tf32.tf32.f32 "
        "{%0,%1,%2,%3}, {%4,%5,%6,%7}, {%8,%9}, {%0,%1,%2,%3};"
        : "+f"(c[0]), "+f"(c[1]), "+f"(c[2]), "+f"(c[3])
        : "r"(__float_as_uint(a[0])), "r"(__float_as_uint(a[1])),
          "r"(__float_as_uint(a[2])), "r"(__float_as_uint(a[3])),
          "r"(__float_as_uint(b[0])), "r"(__float_as_uint(b[1])));
}

// ---------------- embed (float4) ----------------
__global__ void embed_kernel(const float* __restrict__ te, const float* __restrict__ pe,
                             const int* __restrict__ ids, float* __restrict__ x) {
    int row = blockIdx.x;
    int s   = row % NS;
    int id  = ids[row];
    const float4* tp = (const float4*)(te + (size_t)id * ND);
    const float4* pp = (const float4*)(pe + (size_t)s * ND);
    float4* xp = (float4*)(x + (size_t)row * ND);
    for (int i = threadIdx.x; i < 96; i += 128) {
        float4 a = tp[i], b = pp[i];
        xp[i] = make_float4(a.x + b.x, a.y + b.y, a.z + b.z, a.w + b.w);
    }
}

// ---------------- weight packers ----------------
__global__ void pack_pool_w(const float* __restrict__ pw1, float* __restrict__ Wp) {
    int idx = blockIdx.x * 256 + threadIdx.x;
    if (idx < 384 * 384) {
        int k = idx / 384, c = idx % 384;
        int h = c / 96, j = c % 96;
        Wp[idx] = pw1[((size_t)h * 384 + k) * 96 + j];
    }
}

__global__ void pack_qkv_w(const float* __restrict__ wq, const float* __restrict__ wk,
                           const float* __restrict__ wv, float* __restrict__ Wf) {
    int idx = blockIdx.x * 256 + threadIdx.x;
    if (idx >= NL * ND * QLD) return;
    int l   = idx / (ND * QLD);
    int rem = idx - l * (ND * QLD);
    int k   = rem / QLD;
    int c   = rem - k * QLD;
    int sel = c / ND;
    int col = c - sel * ND;
    const float* src = (sel == 0) ? wq : (sel == 1) ? wk : wv;
    Wf[idx] = src[((size_t)l * ND + k) * ND + col];
}

__global__ void pack_qkv_b(const float* __restrict__ bq, const float* __restrict__ bk,
                           const float* __restrict__ bv, float* __restrict__ Bf) {
    int idx = blockIdx.x * 256 + threadIdx.x;
    if (idx >= NL * QLD) return;
    int l = idx / QLD;
    int c = idx - l * QLD;
    int sel = c / ND;
    int col = c - sel * ND;
    const float* src = (sel == 0) ? bq : (sel == 1) ? bk : bv;
    Bf[idx] = src[l * ND + col];
}

// ---------------- layernorm: warp per row, 8 rows per block ----------------
__global__ void ln_kernel(const float* __restrict__ in, float* __restrict__ out,
                          const float* __restrict__ g, const float* __restrict__ b) {
    int row  = blockIdx.x * 8 + (threadIdx.x >> 5);
    int lane = threadIdx.x & 31;
    const float4* p = (const float4*)(in + (size_t)row * ND);
    float4 v[3];
    float s = 0.f;
    #pragma unroll
    for (int i = 0; i < 3; i++) {
        v[i] = p[lane + i * 32];
        s += v[i].x + v[i].y + v[i].z + v[i].w;
    }
    #pragma unroll
    for (int o = 16; o > 0; o >>= 1) s += __shfl_xor_sync(0xffffffffu, s, o);
    float mean = s * (1.f / ND);
    float vs = 0.f;
    #pragma unroll
    for (int i = 0; i < 3; i++) {
        float a0 = v[i].x - mean, a1 = v[i].y - mean;
        float a2 = v[i].z - mean, a3 = v[i].w - mean;
        vs += a0 * a0 + a1 * a1 + a2 * a2 + a3 * a3;
    }
    #pragma unroll
    for (int o = 16; o > 0; o >>= 1) vs += __shfl_xor_sync(0xffffffffu, vs, o);
    float inv = rsqrtf(vs * (1.f / ND) + 1e-5f);
    float4* o4 = (float4*)(out + (size_t)row * ND);
    #pragma unroll
    for (int i = 0; i < 3; i++) {
        float4 gv = ((const float4*)g)[lane + i * 32];
        float4 bv = ((const float4*)b)[lane + i * 32];
        float4 o;
        o.x = (v[i].x - mean) * inv * gv.x + bv.x;
        o.y = (v[i].y - mean) * inv * gv.y + bv.y;
        o.z = (v[i].z - mean) * inv * gv.z + bv.z;
        o.w = (v[i].w - mean) * inv * gv.w + bv.w;
        o4[lane + i * 32] = o;
    }
}

// ================= tf32 TC GEMM: 256x128 tile, BK=16, 256 threads (R8 config) =================
#define GSTRIDE 136
#define GEMM_SMEM_WORDS (2*4096 + 2*16*GSTRIDE)
#define GEMM_SMEM_BYTES (GEMM_SMEM_WORDS * 4)

template<int EPI>
__global__ void __launch_bounds__(256, 1)
gemm_tc_kernel(const float* __restrict__ A, const float* __restrict__ W,
               const float* __restrict__ bias, const float* __restrict__ res,
               float* __restrict__ C, int M, int N, int K) {
    extern __shared__ __align__(16) float dsm[];
    float* As2 = dsm;                       // [2][4096]
    float* Bsf = dsm + 8192;                // [2][16][GSTRIDE]

    const int t    = threadIdx.x;
    const int lane = t & 31;
    const int warp = t >> 5;
    const int wn   = (warp & 1) * 64;
    const int gid  = lane >> 2;
    const int tig  = lane & 3;
    const int brow = blockIdx.y * 256;
    const int bcol = blockIdx.x * 128;

    const int ar  = t;
    const int asw = ((ar & 7) >> 1) & 3;
    const int amb = (ar >> 4) * 128 + (ar & 7) * 16 + ((ar >> 3) & 1);
    const int bkr = t >> 5;
    const int bc  = lane * 4;

    const int afrag = (warp >> 1) * 512 + gid * 16 + ((tig ^ ((gid >> 1) & 3)) << 2);

    const float* Ap = A + (size_t)(brow + ar) * K;

    float acc[4][8][4];
    #pragma unroll
    for (int i = 0; i < 4; i++)
        #pragma unroll
        for (int j = 0; j < 8; j++)
            #pragma unroll
            for (int r = 0; r < 4; r++) acc[i][j][r] = 0.f;

    const int ntiles = K / 16;

    {
        #pragma unroll
        for (int q = 0; q < 4; q++) {
            float4 aq = *(const float4*)&Ap[q * 4];
            const float* ae = &aq.x;
            int base = (q >> 1) * 2048 + amb + (q & 1) * 2;
            #pragma unroll
            for (int j = 0; j < 4; j++)
                As2[base + ((j ^ asw) << 2)] = f2tf(ae[j]);
        }
        float4 b0 = *(const float4*)&W[(size_t)bkr * N + bcol + bc];
        float4 b1 = *(const float4*)&W[(size_t)(bkr + 8) * N + bcol + bc];
        float4 c0, c1;
        c0.x = f2tf(b0.x); c0.y = f2tf(b0.y); c0.z = f2tf(b0.z); c0.w = f2tf(b0.w);
        c1.x = f2tf(b1.x); c1.y = f2tf(b1.y); c1.z = f2tf(b1.z); c1.w = f2tf(b1.w);
        *(float4*)&Bsf[bkr * GSTRIDE + bc]       = c0;
        *(float4*)&Bsf[(bkr + 8) * GSTRIDE + bc] = c1;
    }
    __syncthreads();

    for (int tt = 0; tt < ntiles; tt++) {
        const int cur = tt & 1;
        const int nxt = cur ^ 1;
        const bool more = (tt + 1 < ntiles);
        float4 apre[4], b0, b1;
        if (more) {
            const int k0 = (tt + 1) * 16;
            #pragma unroll
            for (int q = 0; q < 4; q++) apre[q] = *(const float4*)&Ap[k0 + q * 4];
            b0 = *(const float4*)&W[(size_t)(k0 + bkr) * N + bcol + bc];
            b1 = *(const float4*)&W[(size_t)(k0 + bkr + 8) * N + bcol + bc];
        }
        const float* Ab = As2 + cur * 4096;
        const float* Bb = Bsf + cur * (16 * GSTRIDE);
        #pragma unroll
        for (int ks = 0; ks < 2; ks++) {
            float a[4][4], b[8][2];
            #pragma unroll
            for (int mt = 0; mt < 4; mt++) {
                float4 av = *(const float4*)&Ab[ks * 2048 + mt * 128 + afrag];
                a[mt][0] = av.x; a[mt][1] = av.y; a[mt][2] = av.z; a[mt][3] = av.w;
            }
            #pragma unroll
            for (int nt = 0; nt < 8; nt++) {
                const int n0 = wn + nt * 8 + gid;
                b[nt][0] = Bb[(ks * 8 + tig) * GSTRIDE + n0];
                b[nt][1] = Bb[(ks * 8 + tig + 4) * GSTRIDE + n0];
            }
            #pragma unroll
            for (int mt = 0; mt < 4; mt++)
                #pragma unroll
                for (int nt = 0; nt < 8; nt++)
                    mma_tf32(acc[mt][nt], a[mt], b[nt]);
        }
        if (more) {
            float* An = As2 + nxt * 4096;
            #pragma unroll
            for (int q = 0; q < 4; q++) {
                const float* ae = &apre[q].x;
                int base = (q >> 1) * 2048 + amb + (q & 1) * 2;
                #pragma unroll
                for (int j = 0; j < 4; j++)
                    An[base + ((j ^ asw) << 2)] = f2tf(ae[j]);
            }
            float4 c0, c1;
            c0.x = f2tf(b0.x); c0.y = f2tf(b0.y); c0.z = f2tf(b0.z); c0.w = f2tf(b0.w);
            c1.x = f2tf(b1.x); c1.y = f2tf(b1.y); c1.z = f2tf(b1.z); c1.w = f2tf(b1.w);
            float* Bn = Bsf + nxt * (16 * GSTRIDE);
            *(float4*)&Bn[bkr * GSTRIDE + bc]       = c0;
            *(float4*)&Bn[(bkr + 8) * GSTRIDE + bc] = c1;
        }
        __syncthreads();
    }

    const int wm = (warp >> 1) * 64;
    #pragma unroll
    for (int mt = 0; mt < 4; mt++) {
        const int r0 = brow + wm + mt * 16 + gid;
        #pragma unroll
        for (int nt = 0; nt < 8; nt++) {
            const int c0 = bcol + wn + nt * 8 + tig * 2;
            float bx = bias[c0], by = bias[c0 + 1];
            float v00 = acc[mt][nt][0] + bx;
            float v01 = acc[mt][nt][1] + by;
            float v10 = acc[mt][nt][2] + bx;
            float v11 = acc[mt][nt][3] + by;
            if (EPI == 1) {
                v00 = 0.5f * v00 * (1.f + erff(v00 * 0.70710678118654752f));
                v01 = 0.5f * v01 * (1.f + erff(v01 * 0.70710678118654752f));
                v10 = 0.5f * v10 * (1.f + erff(v10 * 0.70710678118654752f));
                v11 = 0.5f * v11 * (1.f + erff(v11 * 0.70710678118654752f));
            } else if (EPI == 2) {
                float2 r0v = *(const float2*)&res[(size_t)r0 * N + c0];
                float2 r1v = *(const float2*)&res[(size_t)(r0 + 8) * N + c0];
                v00 += r0v.x; v01 += r0v.y; v10 += r1v.x; v11 += r1v.y;
            } else if (EPI == 3) {
                v00 = tanhf(v00); v01 = tanhf(v01);
                v10 = tanhf(v10); v11 = tanhf(v11);
            }
            *(float2*)&C[(size_t)r0 * N + c0]       = make_float2(v00, v01);
            *(float2*)&C[(size_t)(r0 + 8) * N + c0] = make_float2(v10, v11);
        }
    }
}

// ---------------- small guarded SGEMM (classifier) ----------------
template<int EPI>
__global__ void gemm_kernel(const float* __restrict__ A, const float* __restrict__ W,
                            const float* __restrict__ bias,
                            float* __restrict__ C, int M, int N, int K) {
    __shared__ float As[16][65];
    __shared__ float Bs[16][64];
    const int brow = blockIdx.y * 64;
    const int bcol = blockIdx.x * 64;
    const int t  = threadIdx.x;
    const int ty = t >> 4, tx = t & 15;
    float acc[4][4] = {};
    for (int k0 = 0; k0 < K; k0 += 16) {
        #pragma unroll
        for (int l = t; l < 1024; l += 256) {
            int r = l >> 4, kk = l & 15;
            int gr = brow + r;
            As[kk][r] = (gr < M && k0 + kk < K) ? A[(size_t)gr * K + k0 + kk] : 0.f;
        }
        #pragma unroll
        for (int l = t; l < 1024; l += 256) {
            int kk = l >> 6, c = l & 63;
            int gc = bcol + c;
            Bs[kk][c] = (gc < N && k0 + kk < K) ? W[(size_t)(k0 + kk) * N + gc] : 0.f;
        }
        __syncthreads();
        #pragma unroll
        for (int kk = 0; kk < 16; kk++) {
            float a[4], bvals[4];
            #pragma unroll
            for (int i = 0; i < 4; i++) a[i] = As[kk][ty * 4 + i];
            #pragma unroll
            for (int j = 0; j < 4; j++) bvals[j] = Bs[kk][tx * 4 + j];
            #pragma unroll
            for (int i = 0; i < 4; i++)
                #pragma unroll
                for (int j = 0; j < 4; j++)
                    acc[i][j] += a[i] * bvals[j];
        }
        __syncthreads();
    }
    #pragma unroll
    for (int i = 0; i < 4; i++) {
        int row = brow + ty * 4 + i;
        if (row >= M) continue;
        #pragma unroll
        for (int j = 0; j < 4; j++) {
            int col = bcol + tx * 4 + j;
            if (col >= N) continue;
            float v = acc[i][j] + bias[col];
            if (EPI == 1) v = 0.5f * v * (1.f + erff(v * 0.70710678118654752f));
            else if (EPI == 3) v = tanhf(v);
            C[(size_t)row * N + col] = v;
        }
    }
}

// ================= tensor-core flash attention: 4 warps x 32 q-rows =================
// B fragments (rel/K/V) shared across 2 m-tiles per warp -> ~35% less smem traffic.
// smem (floats): Qs[32][132] | Ks[32][68] | Rs[32][200] (192 rows valid) |
//                Vs[64][36] | WS[4][32][100] | Mk[64]
#define WSTRIDE 100
#define ATT_SMEM_WORDS 27968
#define ATT_SMEM_BYTES (ATT_SMEM_WORDS * 4)

__global__ void __launch_bounds__(128, 2)
attn_tc_kernel(const float* __restrict__ q, const float* __restrict__ k,
               const float* __restrict__ v, const float* __restrict__ rel,
               const int* __restrict__ ids, float* __restrict__ out) {
    extern __shared__ float sm[];
    float* Qs = sm;                   // [32][132]
    float* Ks = sm + 4224;            // [32][68]
    float* Rs = sm + 6400;            // [32][200]
    float* Vs = sm + 12800;           // [64][36]
    float* WS = sm + 15104;           // [4][32][100]
    int*   Mk = (int*)(sm + 27904);   // [64]

    const int q0 = blockIdx.x * 128;
    const int h  = blockIdx.y;
    const int b  = blockIdx.z;
    const int t    = threadIdx.x;     // 0..127
    const int lane = t & 31;
    const int w    = t >> 5;          // 0..3
    const int gid  = lane >> 2;
    const int tig  = lane & 3;
    float* WSw = WS + w * (32 * WSTRIDE);
    const int j0w = 96 - 32 * w;      // warp band start within block rel band
    const float scale = 0.17677669529663689f;

    // ---- load Q tile (transposed, tf32) ----
    {
        const float* qb = q + ((size_t)(b * NS + q0)) * QLD + h * NDK;
        #pragma unroll
        for (int i = t; i < 1024; i += 128) {
            int r = i >> 3, d0 = (i & 7) * 4;
            float4 x = *(const float4*)&qb[(size_t)r * QLD + d0];
            Qs[(d0 + 0) * 132 + r] = f2tf(x.x);
            Qs[(d0 + 1) * 132 + r] = f2tf(x.y);
            Qs[(d0 + 2) * 132 + r] = f2tf(x.z);
            Qs[(d0 + 3) * 132 + r] = f2tf(x.w);
        }
    }
    __syncthreads();

    // ---- Q fragments for both m-tiles ----
    float af[2][4][4];
    #pragma unroll
    for (int mt = 0; mt < 2; mt++)
        #pragma unroll
        for (int ks = 0; ks < 4; ks++) {
            int kk = ks * 8 + tig;
            int m0 = w * 32 + mt * 16 + gid;
            af[mt][ks][0] = Qs[kk * 132 + m0];
            af[mt][ks][1] = Qs[kk * 132 + m0 + 8];
            af[mt][ks][2] = Qs[(kk + 4) * 132 + m0];
            af[mt][ks][3] = Qs[(kk + 4) * 132 + m0 + 8];
        }

    float mxs[2][2], lss[2][2];
    float oa[2][4][4];
    #pragma unroll
    for (int mt = 0; mt < 2; mt++) {
        mxs[mt][0] = -INFINITY; mxs[mt][1] = -INFINITY;
        lss[mt][0] = 0.f;       lss[mt][1] = 0.f;
        #pragma unroll
        for (int i = 0; i < 4; i++)
            #pragma unroll
            for (int j = 0; j < 4; j++) oa[mt][i][j] = 0.f;
    }

    for (int k0 = 0; k0 < NS; k0 += 64) {
        __syncthreads();
        {
            const float* kb = k + ((size_t)(b * NS + k0)) * QLD + h * NDK;
            const float* vb = v + ((size_t)(b * NS + k0)) * QLD + h * NDK;
            #pragma unroll
            for (int i = t; i < 512; i += 128) {
                int r = i >> 3, d0 = (i & 7) * 4;
                float4 x = *(const float4*)&kb[(size_t)r * QLD + d0];
                Ks[(d0 + 0) * 68 + r] = f2tf(x.x);
                Ks[(d0 + 1) * 68 + r] = f2tf(x.y);
                Ks[(d0 + 2) * 68 + r] = f2tf(x.z);
                Ks[(d0 + 3) * 68 + r] = f2tf(x.w);
                float4 y = *(const float4*)&vb[(size_t)r * QLD + d0];
                float4 z;
                z.x = f2tf(y.x); z.y = f2tf(y.y); z.z = f2tf(y.z); z.w = f2tf(y.w);
                *(float4*)&Vs[r * 36 + d0] = z;
            }
            // rel band: j in [0,192), delta = k0-q0+640+j (row 191 clamped, never read)
            const float* rb = rel;
            #pragma unroll
            for (int i = t; i < 192 * 8; i += 128) {
                int j = i >> 3, d0 = (i & 7) * 4;
                int g = k0 - q0 + 640 + j;
                if (g > 1534) g = 1534;
                float4 x = *(const float4*)&rb[(size_t)g * NDK + d0];
                Rs[(d0 + 0) * 200 + j] = f2tf(x.x);
                Rs[(d0 + 1) * 200 + j] = f2tf(x.y);
                Rs[(d0 + 2) * 200 + j] = f2tf(x.z);
                Rs[(d0 + 3) * 200 + j] = f2tf(x.w);
            }
            if (t < 64) Mk[t] = ids[b * NS + k0 + t];
        }
        __syncthreads();

        // ---- rel-band MMA: [32 x 96] per warp, 3 chunks of 4 n-tiles ----
        #pragma unroll
        for (int chunk = 0; chunk < 3; chunk++) {
            float rc[2][4][4];
            #pragma unroll
            for (int mt = 0; mt < 2; mt++)
                #pragma unroll
                for (int nt = 0; nt < 4; nt++)
                    #pragma unroll
                    for (int e = 0; e < 4; e++) rc[mt][nt][e] = 0.f;
            #pragma unroll
            for (int ks = 0; ks < 4; ks++) {
                int kk = ks * 8 + tig;
                #pragma unroll
                for (int nt = 0; nt < 4; nt++) {
                    int col = j0w + (chunk * 4 + nt) * 8 + gid;
                    float bb[2];
                    bb[0] = Rs[kk * 200 + col];
                    bb[1] = Rs[(kk + 4) * 200 + col];
                    #pragma unroll
                    for (int mt = 0; mt < 2; mt++)
                        mma_tf32(rc[mt][nt], af[mt][ks], bb);
                }
            }
            #pragma unroll
            for (int mt = 0; mt < 2; mt++)
                #pragma unroll
                for (int nt = 0; nt < 4; nt++) {
                    int c0 = (chunk * 4 + nt) * 8 + 2 * tig;
                    int r0 = mt * 16 + gid;
                    WSw[r0 * WSTRIDE + c0]           = rc[mt][nt][0];
                    WSw[r0 * WSTRIDE + c0 + 1]       = rc[mt][nt][1];
                    WSw[(r0 + 8) * WSTRIDE + c0]     = rc[mt][nt][2];
                    WSw[(r0 + 8) * WSTRIDE + c0 + 1] = rc[mt][nt][3];
                }
        }
        __syncwarp();

        // ---- QK MMA: [32 x 64] per warp ----
        float qa[2][8][4];
        #pragma unroll
        for (int mt = 0; mt < 2; mt++)
            #pragma unroll
            for (int nt = 0; nt < 8; nt++)
                #pragma unroll
                for (int e = 0; e < 4; e++) qa[mt][nt][e] = 0.f;
        #pragma unroll
        for (int ks = 0; ks < 4; ks++) {
            int kk = ks * 8 + tig;
            #pragma unroll
            for (int nt = 0; nt < 8; nt++) {
                int col = nt * 8 + gid;
                float bb[2];
                bb[0] = Ks[kk * 68 + col];
                bb[1] = Ks[(kk + 4) * 68 + col];
                #pragma unroll
                for (int mt = 0; mt < 2; mt++)
                    mma_tf32(qa[mt][nt], af[mt][ks], bb);
            }
        }

        // ---- combine + mask: band col for row r, key kl is kl + 31 - r ----
        #pragma unroll
        for (int mt = 0; mt < 2; mt++)
            #pragma unroll
            for (int nt = 0; nt < 8; nt++) {
                int kl0 = nt * 8 + 2 * tig;
                int kl1 = kl0 + 1;
                int rlo = mt * 16 + gid, rhi = rlo + 8;
                bool m0b = (Mk[kl0] == 0), m1b = (Mk[kl1] == 0);
                qa[mt][nt][0] = m0b ? -INFINITY : (qa[mt][nt][0] + WSw[rlo * WSTRIDE + kl0 + 31 - rlo]) * scale;
                qa[mt][nt][1] = m1b ? -INFINITY : (qa[mt][nt][1] + WSw[rlo * WSTRIDE + kl1 + 31 - rlo]) * scale;
                qa[mt][nt][2] = m0b ? -INFINITY : (qa[mt][nt][2] + WSw[rhi * WSTRIDE + kl0 + 31 - rhi]) * scale;
                qa[mt][nt][3] = m1b ? -INFINITY : (qa[mt][nt][3] + WSw[rhi * WSTRIDE + kl1 + 31 - rhi]) * scale;
            }
        __syncwarp();

        // ---- online softmax per m-tile ----
        #pragma unroll
        for (int mt = 0; mt < 2; mt++) {
            float tm_lo = -INFINITY, tm_hi = -INFINITY;
            #pragma unroll
            for (int nt = 0; nt < 8; nt++) {
                tm_lo = fmaxf(tm_lo, fmaxf(qa[mt][nt][0], qa[mt][nt][1]));
                tm_hi = fmaxf(tm_hi, fmaxf(qa[mt][nt][2], qa[mt][nt][3]));
            }
            tm_lo = fmaxf(tm_lo, __shfl_xor_sync(0xffffffffu, tm_lo, 1));
            tm_lo = fmaxf(tm_lo, __shfl_xor_sync(0xffffffffu, tm_lo, 2));
            tm_hi = fmaxf(tm_hi, __shfl_xor_sync(0xffffffffu, tm_hi, 1));
            tm_hi = fmaxf(tm_hi, __shfl_xor_sync(0xffffffffu, tm_hi, 2));

            float nm_lo = fmaxf(mxs[mt][0], tm_lo);
            float nm_hi = fmaxf(mxs[mt][1], tm_hi);
            float c_lo = 1.f, c_hi = 1.f, sum_lo = 0.f, sum_hi = 0.f;
            int rlo = mt * 16 + gid, rhi = rlo + 8;

            if (nm_lo == -INFINITY) {
                #pragma unroll
                for (int nt = 0; nt < 8; nt++) {
                    int c0 = nt * 8 + 2 * tig;
                    WSw[rlo * WSTRIDE + c0] = 0.f; WSw[rlo * WSTRIDE + c0 + 1] = 0.f;
                }
            } else {
                c_lo = __expf(mxs[mt][0] - nm_lo);
                #pragma unroll
                for (int nt = 0; nt < 8; nt++) {
                    int c0 = nt * 8 + 2 * tig;
                    float p0 = __expf(qa[mt][nt][0] - nm_lo);
                    float p1 = __expf(qa[mt][nt][1] - nm_lo);
                    sum_lo += p0 + p1;
                    WSw[rlo * WSTRIDE + c0]     = f2tf(p0);
                    WSw[rlo * WSTRIDE + c0 + 1] = f2tf(p1);
                }
            }
            if (nm_hi == -INFINITY) {
                #pragma unroll
                for (int nt = 0; nt < 8; nt++) {
                    int c0 = nt * 8 + 2 * tig;
                    WSw[rhi * WSTRIDE + c0] = 0.f; WSw[rhi * WSTRIDE + c0 + 1] = 0.f;
                }
            } else {
                c_hi = __expf(mxs[mt][1] - nm_hi);
                #pragma unroll
                for (int nt = 0; nt < 8; nt++) {
                    int c0 = nt * 8 + 2 * tig;
                    float p0 = __expf(qa[mt][nt][2] - nm_hi);
                    float p1 = __expf(qa[mt][nt][3] - nm_hi);
                    sum_hi += p0 + p1;
                    WSw[rhi * WSTRIDE + c0]     = f2tf(p0);
                    WSw[rhi * WSTRIDE + c0 + 1] = f2tf(p1);
                }
            }
            sum_lo += __shfl_xor_sync(0xffffffffu, sum_lo, 1);
            sum_lo += __shfl_xor_sync(0xffffffffu, sum_lo, 2);
            sum_hi += __shfl_xor_sync(0xffffffffu, sum_hi, 1);
            sum_hi += __shfl_xor_sync(0xffffffffu, sum_hi, 2);
            mxs[mt][0] = nm_lo; mxs[mt][1] = nm_hi;
            lss[mt][0] = lss[mt][0] * c_lo + sum_lo;
            lss[mt][1] = lss[mt][1] * c_hi + sum_hi;
            #pragma unroll
            for (int nt = 0; nt < 4; nt++) {
                oa[mt][nt][0] *= c_lo; oa[mt][nt][1] *= c_lo;
                oa[mt][nt][2] *= c_hi; oa[mt][nt][3] *= c_hi;
            }
        }
        __syncwarp();

        // ---- PV MMA: O[32 x 32] += P[32 x 64] @ V[64 x 32] (B shared across mt) ----
        #pragma unroll
        for (int ks = 0; ks < 8; ks++) {
            int kk = ks * 8 + tig;
            float pa[2][4];
            #pragma unroll
            for (int mt = 0; mt < 2; mt++) {
                int r0 = mt * 16 + gid;
                pa[mt][0] = WSw[r0 * WSTRIDE + kk];
                pa[mt][1] = WSw[(r0 + 8) * WSTRIDE + kk];
                pa[mt][2] = WSw[r0 * WSTRIDE + kk + 4];
                pa[mt][3] = WSw[(r0 + 8) * WSTRIDE + kk + 4];
            }
            #pragma unroll
            for (int nt = 0; nt < 4; nt++) {
                int col = nt * 8 + gid;
                float bb[2];
                bb[0] = Vs[kk * 36 + col];
                bb[1] = Vs[(kk + 4) * 36 + col];
                #pragma unroll
                for (int mt = 0; mt < 2; mt++)
                    mma_tf32(oa[mt][nt], pa[mt], bb);
            }
        }
    }

    // ---- finalize ----
    #pragma unroll
    for (int mt = 0; mt < 2; mt++) {
        float inv_lo = (lss[mt][0] > 0.f) ? 1.f / lss[mt][0] : 0.f;
        float inv_hi = (lss[mt][1] > 0.f) ? 1.f / lss[mt][1] : 0.f;
        const int rlo = b * NS + q0 + w * 32 + mt * 16 + gid;
        #pragma unroll
        for (int nt = 0; nt < 4; nt++) {
            int col = h * NDK + nt * 8 + 2 * tig;
            out[(size_t)rlo * ND + col]           = oa[mt][nt][0] * inv_lo;
            out[(size_t)rlo * ND + col + 1]       = oa[mt][nt][1] * inv_lo;
            out[(size_t)(rlo + 8) * ND + col]     = oa[mt][nt][2] * inv_hi;
            out[(size_t)(rlo + 8) * ND + col + 1] = oa[mt][nt][3] * inv_hi;
        }
    }
}

// ---------------- pooling ----------------
__global__ void pool_score_kernel(const float* __restrict__ tmp, const float* __restrict__ pw2,
                                  const float* __restrict__ pb2, float* __restrict__ scores) {
    int gid = blockIdx.x * (blockDim.x >> 5) + (threadIdx.x >> 5);
    if (gid >= 4 * NBS) return;
    int head = gid / NBS;
    int row  = gid - head * NBS;
    int lane = threadIdx.x & 31;
    const float* p = tmp + (size_t)row * 384 + head * 96;
    float s = 0.f;
    for (int j = lane; j < 96; j += 32) s += p[j] * pw2[head * 96 + j];
    #pragma unroll
    for (int o = 16; o > 0; o >>= 1) s += __shfl_xor_sync(0xffffffffu, s, o);
    if (lane == 0) scores[gid] = s + pb2[head];
}

__global__ void pool_kernel(const float* __restrict__ x, const float* __restrict__ scores,
                            const int* __restrict__ ids, float* __restrict__ pooled) {
    const int head = blockIdx.x;
    const int b    = blockIdx.y;
    __shared__ float ps[NS];
    __shared__ float red[8];
    const float* sc = scores + (size_t)head * NBS + (size_t)b * NS;

    float m = -INFINITY;
    for (int s = threadIdx.x; s < NS; s += 256) {
        float val = (ids[b * NS + s] == 0) ? -INFINITY : sc[s];
        ps[s] = val;
        m = fmaxf(m, val);
    }
    #pragma unroll
    for (int o = 16; o > 0; o >>= 1) m = fmaxf(m, __shfl_xor_sync(0xffffffffu, m, o));
    if ((threadIdx.x & 31) == 0) red[threadIdx.x >> 5] = m;
    __syncthreads();
    float M = -INFINITY;
    #pragma unroll
    for (int i = 0; i < 8; i++) M = fmaxf(M, red[i]);
    __syncthreads();

    float sum = 0.f;
    for (int s = threadIdx.x; s < NS; s += 256) {
        float p = __expf(ps[s] - M);
        ps[s] = p;
        sum += p;
    }
    #pragma unroll
    for (int o = 16; o > 0; o >>= 1) sum += __shfl_xor_sync(0xffffffffu, sum, o);
    if ((threadIdx.x & 31) == 0) red[threadIdx.x >> 5] = sum;
    __syncthreads();
    float T = 0.f;
    #pragma unroll
    for (int i = 0; i < 8; i++) T += red[i];
    __syncthreads();
    float inv = 1.f / T;

    for (int d = threadIdx.x; d < ND; d += 256) {
        float acc = 0.f;
        const float* xp = x + (size_t)b * NS * ND + d;
        for (int s = 0; s < NS; s++) acc += ps[s] * xp[(size_t)s * ND];
        pooled[(size_t)b * (4 * ND) + head * ND + d] = acc * inv;
    }
}

// ---------------- dispatchers ----------------
static void run_big_gemm(const float* A, const float* W, const float* bias, const float* res,
                         float* C, int M, int N, int K, int epi) {
    dim3 grid(N / 128, M / 256);
    switch (epi) {
        case 0: gemm_tc_kernel<0><<<grid, 256, GEMM_SMEM_BYTES>>>(A, W, bias, res, C, M, N, K); break;
        case 1: gemm_tc_kernel<1><<<grid, 256, GEMM_SMEM_BYTES>>>(A, W, bias, res, C, M, N, K); break;
        case 2: gemm_tc_kernel<2><<<grid, 256, GEMM_SMEM_BYTES>>>(A, W, bias, res, C, M, N, K); break;
        case 3: gemm_tc_kernel<3><<<grid, 256, GEMM_SMEM_BYTES>>>(A, W, bias, res, C, M, N, K); break;
    }
}

static void run_small_gemm(const float* A, const float* W, const float* bias,
                           float* C, int M, int N, int K, int epi) {
    dim3 grid((N + 63) / 64, (M + 63) / 64);
    switch (epi) {
        case 0: gemm_kernel<0><<<grid, 256>>>(A, W, bias, C, M, N, K); break;
        case 1: gemm_kernel<1><<<grid, 256>>>(A, W, bias, C, M, N, K); break;
        case 3: gemm_kernel<3><<<grid, 256>>>(A, W, bias, C, M, N, K); break;
    }
}

// ---------------- entry ----------------
extern "C" void kernel_launch(void* const* d_in, const int* in_sizes, int n_in,
                              void* d_out, int out_size) {
    const float* te   = (const float*)d_in[0];
    const float* pe   = (const float*)d_in[1];
    const float* wq   = (const float*)d_in[2];
    const float* bq   = (const float*)d_in[3];
    const float* wk   = (const float*)d_in[4];
    const float* bk   = (const float*)d_in[5];
    const float* wv   = (const float*)d_in[6];
    const float* bv   = (const float*)d_in[7];
    const float* wo   = (const float*)d_in[8];
    const float* bo   = (const float*)d_in[9];
    const float* rel  = (const float*)d_in[10];
    const float* g1   = (const float*)d_in[11];
    const float* b1   = (const float*)d_in[12];
    const float* g2   = (const float*)d_in[13];
    const float* b2   = (const float*)d_in[14];
    const float* fw1  = (const float*)d_in[15];
    const float* fb1  = (const float*)d_in[16];
    const float* fw2  = (const float*)d_in[17];
    const float* fb2  = (const float*)d_in[18];
    const float* fg   = (const float*)d_in[19];
    const float* fbn  = (const float*)d_in[20];
    const float* pw1  = (const float*)d_in[21];
    const float* pb1  = (const float*)d_in[22];
    const float* pw2  = (const float*)d_in[23];
    const float* pb2  = (const float*)d_in[24];
    const float* cw1  = (const float*)d_in[25];
    const float* cb1  = (const float*)d_in[26];
    const float* cw2  = (const float*)d_in[27];
    const float* cb2  = (const float*)d_in[28];
    const float* cw3  = (const float*)d_in[29];
    const float* cb3  = (const float*)d_in[30];
    const int*   ids  = (const int*)d_in[31];

    float* S;
    cudaGetSymbolAddress((void**)&S, g_scratch);
    float* X    = S + OFF_X;
    float* HB   = S + OFF_H;
    float* QKV  = S + OFF_QKV;
    float* AB   = S + OFF_A;
    float* FB   = S + OFF_FF;
    float* PT   = S + OFF_PT;
    float* PS   = S + OFF_PS;
    float* PD   = S + OFF_PD;
    float* C1   = S + OFF_C1;
    float* C2   = S + OFF_C2;
    float* PW   = S + OFF_PW;
    float* WQKV = S + OFF_WQKV;
    float* BQKV = S + OFF_BQKV;

    cudaFuncSetAttribute(attn_tc_kernel,
                         cudaFuncAttributeMaxDynamicSharedMemorySize, ATT_SMEM_BYTES);
    cudaFuncSetAttribute(gemm_tc_kernel<0>,
                         cudaFuncAttributeMaxDynamicSharedMemorySize, GEMM_SMEM_BYTES);
    cudaFuncSetAttribute(gemm_tc_kernel<1>,
                         cudaFuncAttributeMaxDynamicSharedMemorySize, GEMM_SMEM_BYTES);
    cudaFuncSetAttribute(gemm_tc_kernel<2>,
                         cudaFuncAttributeMaxDynamicSharedMemorySize, GEMM_SMEM_BYTES);
    cudaFuncSetAttribute(gemm_tc_kernel<3>,
                         cudaFuncAttributeMaxDynamicSharedMemorySize, GEMM_SMEM_BYTES);

    pack_qkv_w<<<(NL * ND * QLD + 255) / 256, 256>>>(wq, wk, wv, WQKV);
    pack_qkv_b<<<(NL * QLD + 255) / 256, 256>>>(bq, bk, bv, BQKV);
    pack_pool_w<<<576, 256>>>(pw1, PW);

    embed_kernel<<<NBS, 128>>>(te, pe, ids, X);

    for (int l = 0; l < NL; l++) {
        const size_t wOff = (size_t)l * ND * ND;
        const size_t dOff = (size_t)l * ND;
        ln_kernel<<<NBS / 8, 256>>>(X, HB, g1 + dOff, b1 + dOff);
        run_big_gemm(HB, WQKV + (size_t)l * ND * QLD, BQKV + (size_t)l * QLD, nullptr,
                     QKV, NBS, QLD, ND, 0);
        attn_tc_kernel<<<dim3(NS / 128, NH, NB), 128, ATT_SMEM_BYTES>>>(
            QKV, QKV + ND, QKV + 2 * ND, rel + (size_t)l * (2 * NML - 1) * NDK, ids, AB);
        run_big_gemm(AB, wo + wOff, bo + dOff, X, X, NBS, ND, ND, 2);
        ln_kernel<<<NBS / 8, 256>>>(X, HB, g2 + dOff, b2 + dOff);
        run_big_gemm(HB, fw1 + (size_t)l * ND * NFF, fb1 + (size_t)l * NFF, nullptr, FB,
                     NBS, NFF, ND, 1);
        run_big_gemm(FB, fw2 + (size_t)l * NFF * ND, fb2 + dOff, X, X, NBS, ND, NFF, 2);
    }

    ln_kernel<<<NBS / 8, 256>>>(X, HB, fg, fbn);

    run_big_gemm(HB, PW, pb1, nullptr, PT, NBS, 384, 384, 3);
    pool_score_kernel<<<(4 * NBS + 3) / 4, 128>>>(PT, pw2, pb2, PS);
    pool_kernel<<<dim3(4, NB), 256>>>(HB, PS, ids, PD);

    run_small_gemm(PD, cw1, cb1, C1, NB, ND, 4 * ND, 1);
    run_small_gemm(C1, cw2, cb2, C2, NB, 192, ND, 1);
    run_small_gemm(C2, cw3, cb3, (float*)d_out, NB, NNC, 192, 0);
}

// round 16
// speedup vs baseline: 1.1418x; 1.0157x over previous
#include <cuda_runtime.h>
#include <math.h>
#include <stdint.h>

// ---------------- problem dims ----------------
#define NB   16
#define NS   768
#define ND   384
#define NH   12
#define NDK  32
#define NFF  1024
#define NL   6
#define NML  768
#define NNC  10
#define NBS  (NB*NS)          // 12288 rows
#define QLD  1152             // fused QKV row stride

// ---------------- scratch ----------------
#define OFF_X    ((size_t)0)
#define OFF_H    (OFF_X   + (size_t)NBS*ND)
#define OFF_QKV  (OFF_H   + (size_t)NBS*ND)
#define OFF_A    (OFF_QKV + (size_t)NBS*QLD)
#define OFF_FF   (OFF_A   + (size_t)NBS*ND)
#define OFF_PT   (OFF_FF  + (size_t)NBS*NFF)
#define OFF_PS   (OFF_PT  + (size_t)NBS*384)
#define OFF_PD   (OFF_PS  + (size_t)4*NBS)
#define OFF_C1   (OFF_PD  + (size_t)NB*4*ND)
#define OFF_C2   (OFF_C1  + (size_t)NB*ND)
#define OFF_PW   (OFF_C2  + (size_t)NB*192)
#define OFF_WQKV (OFF_PW  + (size_t)384*384)
#define OFF_BQKV (OFF_WQKV + (size_t)NL*ND*QLD)
#define SCRATCH_TOTAL (OFF_BQKV + (size_t)NL*QLD)

static __device__ float g_scratch[SCRATCH_TOTAL];

// ---------------- tf32 helpers ----------------
__device__ __forceinline__ float f2tf(float f) {
    uint32_t u;
    asm("cvt.rna.tf32.f32 %0, %1;" : "=r"(u) : "f"(f));
    return __uint_as_float(u);
}

__device__ __forceinline__ void mma_tf32(float* c, const float* a, const float* b) {
    asm volatile(
        "mma.sync.aligned.m16n8k8.row.col.f32.tf32.tf32.f32 "
        "{%0,%1,%2,%3}, {%4,%5,%6,%7}, {%8,%9}, {%0,%1,%2,%3};"
        : "+f"(c[0]), "+f"(c[1]), "+f"(c[2]), "+f"(c[3])
        : "r"(__float_as_uint(a[0])), "r"(__float_as_uint(a[1])),
          "r"(__float_as_uint(a[2])), "r"(__float_as_uint(a[3])),
          "r"(__float_as_uint(b[0])), "r"(__float_as_uint(b[1])));
}

// ---------------- embed (float4) ----------------
__global__ void embed_kernel(const float* __restrict__ te, const float* __restrict__ pe,
                             const int* __restrict__ ids, float* __restrict__ x) {
    int row = blockIdx.x;
    int s   = row % NS;
    int id  = ids[row];
    const float4* tp = (const float4*)(te + (size_t)id * ND);
    const float4* pp = (const float4*)(pe + (size_t)s * ND);
    float4* xp = (float4*)(x + (size_t)row * ND);
    for (int i = threadIdx.x; i < 96; i += 128) {
        float4 a = tp[i], b = pp[i];
        xp[i] = make_float4(a.x + b.x, a.y + b.y, a.z + b.z, a.w + b.w);
    }
}

// ---------------- weight packers ----------------
__global__ void pack_pool_w(const float* __restrict__ pw1, float* __restrict__ Wp) {
    int idx = blockIdx.x * 256 + threadIdx.x;
    if (idx < 384 * 384) {
        int k = idx / 384, c = idx % 384;
        int h = c / 96, j = c % 96;
        Wp[idx] = pw1[((size_t)h * 384 + k) * 96 + j];
    }
}

__global__ void pack_qkv_w(const float* __restrict__ wq, const float* __restrict__ wk,
                           const float* __restrict__ wv, float* __restrict__ Wf) {
    int idx = blockIdx.x * 256 + threadIdx.x;
    if (idx >= NL * ND * QLD) return;
    int l   = idx / (ND * QLD);
    int rem = idx - l * (ND * QLD);
    int k   = rem / QLD;
    int c   = rem - k * QLD;
    int sel = c / ND;
    int col = c - sel * ND;
    const float* src = (sel == 0) ? wq : (sel == 1) ? wk : wv;
    Wf[idx] = src[((size_t)l * ND + k) * ND + col];
}

__global__ void pack_qkv_b(const float* __restrict__ bq, const float* __restrict__ bk,
                           const float* __restrict__ bv, float* __restrict__ Bf) {
    int idx = blockIdx.x * 256 + threadIdx.x;
    if (idx >= NL * QLD) return;
    int l = idx / QLD;
    int c = idx - l * QLD;
    int sel = c / ND;
    int col = c - sel * ND;
    const float* src = (sel == 0) ? bq : (sel == 1) ? bk : bv;
    Bf[idx] = src[l * ND + col];
}

// ---------------- layernorm: warp per row, 8 rows per block ----------------
__global__ void ln_kernel(const float* __restrict__ in, float* __restrict__ out,
                          const float* __restrict__ g, const float* __restrict__ b) {
    int row  = blockIdx.x * 8 + (threadIdx.x >> 5);
    int lane = threadIdx.x & 31;
    const float4* p = (const float4*)(in + (size_t)row * ND);
    float4 v[3];
    float s = 0.f;
    #pragma unroll
    for (int i = 0; i < 3; i++) {
        v[i] = p[lane + i * 32];
        s += v[i].x + v[i].y + v[i].z + v[i].w;
    }
    #pragma unroll
    for (int o = 16; o > 0; o >>= 1) s += __shfl_xor_sync(0xffffffffu, s, o);
    float mean = s * (1.f / ND);
    float vs = 0.f;
    #pragma unroll
    for (int i = 0; i < 3; i++) {
        float a0 = v[i].x - mean, a1 = v[i].y - mean;
        float a2 = v[i].z - mean, a3 = v[i].w - mean;
        vs += a0 * a0 + a1 * a1 + a2 * a2 + a3 * a3;
    }
    #pragma unroll
    for (int o = 16; o > 0; o >>= 1) vs += __shfl_xor_sync(0xffffffffu, vs, o);
    float inv = rsqrtf(vs * (1.f / ND) + 1e-5f);
    float4* o4 = (float4*)(out + (size_t)row * ND);
    #pragma unroll
    for (int i = 0; i < 3; i++) {
        float4 gv = ((const float4*)g)[lane + i * 32];
        float4 bv = ((const float4*)b)[lane + i * 32];
        float4 o;
        o.x = (v[i].x - mean) * inv * gv.x + bv.x;
        o.y = (v[i].y - mean) * inv * gv.y + bv.y;
        o.z = (v[i].z - mean) * inv * gv.z + bv.z;
        o.w = (v[i].w - mean) * inv * gv.w + bv.w;
        o4[lane + i * 32] = o;
    }
}

// ================= tf32 TC GEMM: 256x128 tile, BK=16, 256 threads (R8 config) =================
#define GSTRIDE 136
#define GEMM_SMEM_WORDS (2*4096 + 2*16*GSTRIDE)
#define GEMM_SMEM_BYTES (GEMM_SMEM_WORDS * 4)

template<int EPI>
__global__ void __launch_bounds__(256, 1)
gemm_tc_kernel(const float* __restrict__ A, const float* __restrict__ W,
               const float* __restrict__ bias, const float* __restrict__ res,
               float* __restrict__ C, int M, int N, int K) {
    extern __shared__ __align__(16) float dsm[];
    float* As2 = dsm;                       // [2][4096]
    float* Bsf = dsm + 8192;                // [2][16][GSTRIDE]

    const int t    = threadIdx.x;
    const int lane = t & 31;
    const int warp = t >> 5;
    const int wn   = (warp & 1) * 64;
    const int gid  = lane >> 2;
    const int tig  = lane & 3;
    const int brow = blockIdx.y * 256;
    const int bcol = blockIdx.x * 128;

    const int ar  = t;
    const int asw = ((ar & 7) >> 1) & 3;
    const int amb = (ar >> 4) * 128 + (ar & 7) * 16 + ((ar >> 3) & 1);
    const int bkr = t >> 5;
    const int bc  = lane * 4;

    const int afrag = (warp >> 1) * 512 + gid * 16 + ((tig ^ ((gid >> 1) & 3)) << 2);

    const float* Ap = A + (size_t)(brow + ar) * K;

    float acc[4][8][4];
    #pragma unroll
    for (int i = 0; i < 4; i++)
        #pragma unroll
        for (int j = 0; j < 8; j++)
            #pragma unroll
            for (int r = 0; r < 4; r++) acc[i][j][r] = 0.f;

    const int ntiles = K / 16;

    {
        #pragma unroll
        for (int q = 0; q < 4; q++) {
            float4 aq = *(const float4*)&Ap[q * 4];
            const float* ae = &aq.x;
            int base = (q >> 1) * 2048 + amb + (q & 1) * 2;
            #pragma unroll
            for (int j = 0; j < 4; j++)
                As2[base + ((j ^ asw) << 2)] = f2tf(ae[j]);
        }
        float4 b0 = *(const float4*)&W[(size_t)bkr * N + bcol + bc];
        float4 b1 = *(const float4*)&W[(size_t)(bkr + 8) * N + bcol + bc];
        float4 c0, c1;
        c0.x = f2tf(b0.x); c0.y = f2tf(b0.y); c0.z = f2tf(b0.z); c0.w = f2tf(b0.w);
        c1.x = f2tf(b1.x); c1.y = f2tf(b1.y); c1.z = f2tf(b1.z); c1.w = f2tf(b1.w);
        *(float4*)&Bsf[bkr * GSTRIDE + bc]       = c0;
        *(float4*)&Bsf[(bkr + 8) * GSTRIDE + bc] = c1;
    }
    __syncthreads();

    for (int tt = 0; tt < ntiles; tt++) {
        const int cur = tt & 1;
        const int nxt = cur ^ 1;
        const bool more = (tt + 1 < ntiles);
        float4 apre[4], b0, b1;
        if (more) {
            const int k0 = (tt + 1) * 16;
            #pragma unroll
            for (int q = 0; q < 4; q++) apre[q] = *(const float4*)&Ap[k0 + q * 4];
            b0 = *(const float4*)&W[(size_t)(k0 + bkr) * N + bcol + bc];
            b1 = *(const float4*)&W[(size_t)(k0 + bkr + 8) * N + bcol + bc];
        }
        const float* Ab = As2 + cur * 4096;
        const float* Bb = Bsf + cur * (16 * GSTRIDE);
        #pragma unroll
        for (int ks = 0; ks < 2; ks++) {
            float a[4][4], b[8][2];
            #pragma unroll
            for (int mt = 0; mt < 4; mt++) {
                float4 av = *(const float4*)&Ab[ks * 2048 + mt * 128 + afrag];
                a[mt][0] = av.x; a[mt][1] = av.y; a[mt][2] = av.z; a[mt][3] = av.w;
            }
            #pragma unroll
            for (int nt = 0; nt < 8; nt++) {
                const int n0 = wn + nt * 8 + gid;
                b[nt][0] = Bb[(ks * 8 + tig) * GSTRIDE + n0];
                b[nt][1] = Bb[(ks * 8 + tig + 4) * GSTRIDE + n0];
            }
            #pragma unroll
            for (int mt = 0; mt < 4; mt++)
                #pragma unroll
                for (int nt = 0; nt < 8; nt++)
                    mma_tf32(acc[mt][nt], a[mt], b[nt]);
        }
        if (more) {
            float* An = As2 + nxt * 4096;
            #pragma unroll
            for (int q = 0; q < 4; q++) {
                const float* ae = &apre[q].x;
                int base = (q >> 1) * 2048 + amb + (q & 1) * 2;
                #pragma unroll
                for (int j = 0; j < 4; j++)
                    An[base + ((j ^ asw) << 2)] = f2tf(ae[j]);
            }
            float4 c0, c1;
            c0.x = f2tf(b0.x); c0.y = f2tf(b0.y); c0.z = f2tf(b0.z); c0.w = f2tf(b0.w);
            c1.x = f2tf(b1.x); c1.y = f2tf(b1.y); c1.z = f2tf(b1.z); c1.w = f2tf(b1.w);
            float* Bn = Bsf + nxt * (16 * GSTRIDE);
            *(float4*)&Bn[bkr * GSTRIDE + bc]       = c0;
            *(float4*)&Bn[(bkr + 8) * GSTRIDE + bc] = c1;
        }
        __syncthreads();
    }

    const int wm = (warp >> 1) * 64;
    #pragma unroll
    for (int mt = 0; mt < 4; mt++) {
        const int r0 = brow + wm + mt * 16 + gid;
        #pragma unroll
        for (int nt = 0; nt < 8; nt++) {
            const int c0 = bcol + wn + nt * 8 + tig * 2;
            float bx = bias[c0], by = bias[c0 + 1];
            float v00 = acc[mt][nt][0] + bx;
            float v01 = acc[mt][nt][1] + by;
            float v10 = acc[mt][nt][2] + bx;
            float v11 = acc[mt][nt][3] + by;
            if (EPI == 1) {
                v00 = 0.5f * v00 * (1.f + erff(v00 * 0.70710678118654752f));
                v01 = 0.5f * v01 * (1.f + erff(v01 * 0.70710678118654752f));
                v10 = 0.5f * v10 * (1.f + erff(v10 * 0.70710678118654752f));
                v11 = 0.5f * v11 * (1.f + erff(v11 * 0.70710678118654752f));
            } else if (EPI == 2) {
                float2 r0v = *(const float2*)&res[(size_t)r0 * N + c0];
                float2 r1v = *(const float2*)&res[(size_t)(r0 + 8) * N + c0];
                v00 += r0v.x; v01 += r0v.y; v10 += r1v.x; v11 += r1v.y;
            } else if (EPI == 3) {
                v00 = tanhf(v00); v01 = tanhf(v01);
                v10 = tanhf(v10); v11 = tanhf(v11);
            }
            *(float2*)&C[(size_t)r0 * N + c0]       = make_float2(v00, v01);
            *(float2*)&C[(size_t)(r0 + 8) * N + c0] = make_float2(v10, v11);
        }
    }
}

// ---------------- small guarded SGEMM (classifier) ----------------
template<int EPI>
__global__ void gemm_kernel(const float* __restrict__ A, const float* __restrict__ W,
                            const float* __restrict__ bias,
                            float* __restrict__ C, int M, int N, int K) {
    __shared__ float As[16][65];
    __shared__ float Bs[16][64];
    const int brow = blockIdx.y * 64;
    const int bcol = blockIdx.x * 64;
    const int t  = threadIdx.x;
    const int ty = t >> 4, tx = t & 15;
    float acc[4][4] = {};
    for (int k0 = 0; k0 < K; k0 += 16) {
        #pragma unroll
        for (int l = t; l < 1024; l += 256) {
            int r = l >> 4, kk = l & 15;
            int gr = brow + r;
            As[kk][r] = (gr < M && k0 + kk < K) ? A[(size_t)gr * K + k0 + kk] : 0.f;
        }
        #pragma unroll
        for (int l = t; l < 1024; l += 256) {
            int kk = l >> 6, c = l & 63;
            int gc = bcol + c;
            Bs[kk][c] = (gc < N && k0 + kk < K) ? W[(size_t)(k0 + kk) * N + gc] : 0.f;
        }
        __syncthreads();
        #pragma unroll
        for (int kk = 0; kk < 16; kk++) {
            float a[4], bvals[4];
            #pragma unroll
            for (int i = 0; i < 4; i++) a[i] = As[kk][ty * 4 + i];
            #pragma unroll
            for (int j = 0; j < 4; j++) bvals[j] = Bs[kk][tx * 4 + j];
            #pragma unroll
            for (int i = 0; i < 4; i++)
                #pragma unroll
                for (int j = 0; j < 4; j++)
                    acc[i][j] += a[i] * bvals[j];
        }
        __syncthreads();
    }
    #pragma unroll
    for (int i = 0; i < 4; i++) {
        int row = brow + ty * 4 + i;
        if (row >= M) continue;
        #pragma unroll
        for (int j = 0; j < 4; j++) {
            int col = bcol + tx * 4 + j;
            if (col >= N) continue;
            float v = acc[i][j] + bias[col];
            if (EPI == 1) v = 0.5f * v * (1.f + erff(v * 0.70710678118654752f));
            else if (EPI == 3) v = tanhf(v);
            C[(size_t)row * N + col] = v;
        }
    }
}

// ================= tensor-core flash attention: 4 warps x 32 q-rows, reg-pipelined =================
// Next tile's K/V/rel loaded into registers at iteration top, stored to smem after compute.
#define WSTRIDE 100
#define ATT_SMEM_WORDS 27968
#define ATT_SMEM_BYTES (ATT_SMEM_WORDS * 4)

__global__ void __launch_bounds__(128, 2)
attn_tc_kernel(const float* __restrict__ q, const float* __restrict__ k,
               const float* __restrict__ v, const float* __restrict__ rel,
               const int* __restrict__ ids, float* __restrict__ out) {
    extern __shared__ float sm[];
    float* Qs = sm;                   // [32][132]
    float* Ks = sm + 4224;            // [32][68]
    float* Rs = sm + 6400;            // [32][200]
    float* Vs = sm + 12800;           // [64][36]
    float* WS = sm + 15104;           // [4][32][100]
    int*   Mk = (int*)(sm + 27904);   // [64]

    const int q0 = blockIdx.x * 128;
    const int h  = blockIdx.y;
    const int b  = blockIdx.z;
    const int t    = threadIdx.x;     // 0..127
    const int lane = t & 31;
    const int w    = t >> 5;          // 0..3
    const int gid  = lane >> 2;
    const int tig  = lane & 3;
    float* WSw = WS + w * (32 * WSTRIDE);
    const int j0w = 96 - 32 * w;
    const float scale = 0.17677669529663689f;

    // thread-local load mapping (constant across iterations)
    const int kvr = t >> 3;           // K/V row base (0..15), +16*j
    const int kvd = (t & 7) * 4;      // d0
    const float* kbase = k + ((size_t)(b * NS)) * QLD + h * NDK + (size_t)kvr * QLD + kvd;
    const float* vbase = v + ((size_t)(b * NS)) * QLD + h * NDK + (size_t)kvr * QLD + kvd;

    // ---- load Q tile (transposed, tf32) ----
    {
        const float* qb = q + ((size_t)(b * NS + q0)) * QLD + h * NDK;
        #pragma unroll
        for (int i = t; i < 1024; i += 128) {
            int r = i >> 3, d0 = (i & 7) * 4;
            float4 x = *(const float4*)&qb[(size_t)r * QLD + d0];
            Qs[(d0 + 0) * 132 + r] = f2tf(x.x);
            Qs[(d0 + 1) * 132 + r] = f2tf(x.y);
            Qs[(d0 + 2) * 132 + r] = f2tf(x.z);
            Qs[(d0 + 3) * 132 + r] = f2tf(x.w);
        }
    }

    // ---- prefetch registers ----
    float4 rK[4], rV[4], rR[12];
    int rM = 0;

    // prologue: tile 0
    {
        #pragma unroll
        for (int j = 0; j < 4; j++) {
            rK[j] = *(const float4*)&kbase[(size_t)(j * 16) * QLD];
            rV[j] = *(const float4*)&vbase[(size_t)(j * 16) * QLD];
        }
        #pragma unroll
        for (int j = 0; j < 12; j++) {
            int i = t + j * 128;
            int row = i >> 3, d0 = (i & 7) * 4;
            int g = -q0 + 640 + row;
            if (g > 1534) g = 1534;
            rR[j] = *(const float4*)&rel[(size_t)g * NDK + d0];
        }
        if (t < 64) rM = ids[b * NS + t];
    }
    __syncthreads();   // Qs ready

    // ---- Q fragments ----
    float af[2][4][4];
    #pragma unroll
    for (int mt = 0; mt < 2; mt++)
        #pragma unroll
        for (int ks = 0; ks < 4; ks++) {
            int kk = ks * 8 + tig;
            int m0 = w * 32 + mt * 16 + gid;
            af[mt][ks][0] = Qs[kk * 132 + m0];
            af[mt][ks][1] = Qs[kk * 132 + m0 + 8];
            af[mt][ks][2] = Qs[(kk + 4) * 132 + m0];
            af[mt][ks][3] = Qs[(kk + 4) * 132 + m0 + 8];
        }

    // store tile 0 to smem
    {
        #pragma unroll
        for (int j = 0; j < 4; j++) {
            int r = kvr + j * 16;
            Ks[(kvd + 0) * 68 + r] = f2tf(rK[j].x);
            Ks[(kvd + 1) * 68 + r] = f2tf(rK[j].y);
            Ks[(kvd + 2) * 68 + r] = f2tf(rK[j].z);
            Ks[(kvd + 3) * 68 + r] = f2tf(rK[j].w);
            float4 z;
            z.x = f2tf(rV[j].x); z.y = f2tf(rV[j].y);
            z.z = f2tf(rV[j].z); z.w = f2tf(rV[j].w);
            *(float4*)&Vs[r * 36 + kvd] = z;
        }
        #pragma unroll
        for (int j = 0; j < 12; j++) {
            int i = t + j * 128;
            int row = i >> 3, d0 = (i & 7) * 4;
            Rs[(d0 + 0) * 200 + row] = f2tf(rR[j].x);
            Rs[(d0 + 1) * 200 + row] = f2tf(rR[j].y);
            Rs[(d0 + 2) * 200 + row] = f2tf(rR[j].z);
            Rs[(d0 + 3) * 200 + row] = f2tf(rR[j].w);
        }
        if (t < 64) Mk[t] = rM;
    }
    __syncthreads();

    float mxs[2][2], lss[2][2];
    float oa[2][4][4];
    #pragma unroll
    for (int mt = 0; mt < 2; mt++) {
        mxs[mt][0] = -INFINITY; mxs[mt][1] = -INFINITY;
        lss[mt][0] = 0.f;       lss[mt][1] = 0.f;
        #pragma unroll
        for (int i = 0; i < 4; i++)
            #pragma unroll
            for (int j = 0; j < 4; j++) oa[mt][i][j] = 0.f;
    }

    for (int k0 = 0; k0 < NS; k0 += 64) {
        const bool more = (k0 + 64 < NS);
        // ---- prefetch next tile into registers (latency hidden by compute below) ----
        if (more) {
            const int kn = k0 + 64;
            #pragma unroll
            for (int j = 0; j < 4; j++) {
                rK[j] = *(const float4*)&kbase[(size_t)(kn + j * 16) * QLD];
                rV[j] = *(const float4*)&vbase[(size_t)(kn + j * 16) * QLD];
            }
            #pragma unroll
            for (int j = 0; j < 12; j++) {
                int i = t + j * 128;
                int row = i >> 3, d0 = (i & 7) * 4;
                int g = kn - q0 + 640 + row;
                if (g > 1534) g = 1534;
                rR[j] = *(const float4*)&rel[(size_t)g * NDK + d0];
            }
            if (t < 64) rM = ids[b * NS + kn + t];
        }

        // ---- rel-band MMA: [32 x 96] per warp, 3 chunks of 4 n-tiles ----
        #pragma unroll
        for (int chunk = 0; chunk < 3; chunk++) {
            float rc[2][4][4];
            #pragma unroll
            for (int mt = 0; mt < 2; mt++)
                #pragma unroll
                for (int nt = 0; nt < 4; nt++)
                    #pragma unroll
                    for (int e = 0; e < 4; e++) rc[mt][nt][e] = 0.f;
            #pragma unroll
            for (int ks = 0; ks < 4; ks++) {
                int kk = ks * 8 + tig;
                #pragma unroll
                for (int nt = 0; nt < 4; nt++) {
                    int col = j0w + (chunk * 4 + nt) * 8 + gid;
                    float bb[2];
                    bb[0] = Rs[kk * 200 + col];
                    bb[1] = Rs[(kk + 4) * 200 + col];
                    #pragma unroll
                    for (int mt = 0; mt < 2; mt++)
                        mma_tf32(rc[mt][nt], af[mt][ks], bb);
                }
            }
            #pragma unroll
            for (int mt = 0; mt < 2; mt++)
                #pragma unroll
                for (int nt = 0; nt < 4; nt++) {
                    int c0 = (chunk * 4 + nt) * 8 + 2 * tig;
                    int r0 = mt * 16 + gid;
                    WSw[r0 * WSTRIDE + c0]           = rc[mt][nt][0];
                    WSw[r0 * WSTRIDE + c0 + 1]       = rc[mt][nt][1];
                    WSw[(r0 + 8) * WSTRIDE + c0]     = rc[mt][nt][2];
                    WSw[(r0 + 8) * WSTRIDE + c0 + 1] = rc[mt][nt][3];
                }
        }
        __syncwarp();

        // ---- QK MMA: [32 x 64] per warp ----
        float qa[2][8][4];
        #pragma unroll
        for (int mt = 0; mt < 2; mt++)
            #pragma unroll
            for (int nt = 0; nt < 8; nt++)
                #pragma unroll
                for (int e = 0; e < 4; e++) qa[mt][nt][e] = 0.f;
        #pragma unroll
        for (int ks = 0; ks < 4; ks++) {
            int kk = ks * 8 + tig;
            #pragma unroll
            for (int nt = 0; nt < 8; nt++) {
                int col = nt * 8 + gid;
                float bb[2];
                bb[0] = Ks[kk * 68 + col];
                bb[1] = Ks[(kk + 4) * 68 + col];
                #pragma unroll
                for (int mt = 0; mt < 2; mt++)
                    mma_tf32(qa[mt][nt], af[mt][ks], bb);
            }
        }

        // ---- combine + mask ----
        #pragma unroll
        for (int mt = 0; mt < 2; mt++)
            #pragma unroll
            for (int nt = 0; nt < 8; nt++) {
                int kl0 = nt * 8 + 2 * tig;
                int kl1 = kl0 + 1;
                int rlo = mt * 16 + gid, rhi = rlo + 8;
                bool m0b = (Mk[kl0] == 0), m1b = (Mk[kl1] == 0);
                qa[mt][nt][0] = m0b ? -INFINITY : (qa[mt][nt][0] + WSw[rlo * WSTRIDE + kl0 + 31 - rlo]) * scale;
                qa[mt][nt][1] = m1b ? -INFINITY : (qa[mt][nt][1] + WSw[rlo * WSTRIDE + kl1 + 31 - rlo]) * scale;
                qa[mt][nt][2] = m0b ? -INFINITY : (qa[mt][nt][2] + WSw[rhi * WSTRIDE + kl0 + 31 - rhi]) * scale;
                qa[mt][nt][3] = m1b ? -INFINITY : (qa[mt][nt][3] + WSw[rhi * WSTRIDE + kl1 + 31 - rhi]) * scale;
            }
        __syncwarp();

        // ---- online softmax per m-tile ----
        #pragma unroll
        for (int mt = 0; mt < 2; mt++) {
            float tm_lo = -INFINITY, tm_hi = -INFINITY;
            #pragma unroll
            for (int nt = 0; nt < 8; nt++) {
                tm_lo = fmaxf(tm_lo, fmaxf(qa[mt][nt][0], qa[mt][nt][1]));
                tm_hi = fmaxf(tm_hi, fmaxf(qa[mt][nt][2], qa[mt][nt][3]));
            }
            tm_lo = fmaxf(tm_lo, __shfl_xor_sync(0xffffffffu, tm_lo, 1));
            tm_lo = fmaxf(tm_lo, __shfl_xor_sync(0xffffffffu, tm_lo, 2));
            tm_hi = fmaxf(tm_hi, __shfl_xor_sync(0xffffffffu, tm_hi, 1));
            tm_hi = fmaxf(tm_hi, __shfl_xor_sync(0xffffffffu, tm_hi, 2));

            float nm_lo = fmaxf(mxs[mt][0], tm_lo);
            float nm_hi = fmaxf(mxs[mt][1], tm_hi);
            float c_lo = 1.f, c_hi = 1.f, sum_lo = 0.f, sum_hi = 0.f;
            int rlo = mt * 16 + gid, rhi = rlo + 8;

            if (nm_lo == -INFINITY) {
                #pragma unroll
                for (int nt = 0; nt < 8; nt++) {
                    int c0 = nt * 8 + 2 * tig;
                    WSw[rlo * WSTRIDE + c0] = 0.f; WSw[rlo * WSTRIDE + c0 + 1] = 0.f;
                }
            } else {
                c_lo = __expf(mxs[mt][0] - nm_lo);
                #pragma unroll
                for (int nt = 0; nt < 8; nt++) {
                    int c0 = nt * 8 + 2 * tig;
                    float p0 = __expf(qa[mt][nt][0] - nm_lo);
                    float p1 = __expf(qa[mt][nt][1] - nm_lo);
                    sum_lo += p0 + p1;
                    WSw[rlo * WSTRIDE + c0]     = f2tf(p0);
                    WSw[rlo * WSTRIDE + c0 + 1] = f2tf(p1);
                }
            }
            if (nm_hi == -INFINITY) {
                #pragma unroll
                for (int nt = 0; nt < 8; nt++) {
                    int c0 = nt * 8 + 2 * tig;
                    WSw[rhi * WSTRIDE + c0] = 0.f; WSw[rhi * WSTRIDE + c0 + 1] = 0.f;
                }
            } else {
                c_hi = __expf(mxs[mt][1] - nm_hi);
                #pragma unroll
                for (int nt = 0; nt < 8; nt++) {
                    int c0 = nt * 8 + 2 * tig;
                    float p0 = __expf(qa[mt][nt][2] - nm_hi);
                    float p1 = __expf(qa[mt][nt][3] - nm_hi);
                    sum_hi += p0 + p1;
                    WSw[rhi * WSTRIDE + c0]     = f2tf(p0);
                    WSw[rhi * WSTRIDE + c0 + 1] = f2tf(p1);
                }
            }
            sum_lo += __shfl_xor_sync(0xffffffffu, sum_lo, 1);
            sum_lo += __shfl_xor_sync(0xffffffffu, sum_lo, 2);
            sum_hi += __shfl_xor_sync(0xffffffffu, sum_hi, 1);
            sum_hi += __shfl_xor_sync(0xffffffffu, sum_hi, 2);
            mxs[mt][0] = nm_lo; mxs[mt][1] = nm_hi;
            lss[mt][0] = lss[mt][0] * c_lo + sum_lo;
            lss[mt][1] = lss[mt][1] * c_hi + sum_hi;
            #pragma unroll
            for (int nt = 0; nt < 4; nt++) {
                oa[mt][nt][0] *= c_lo; oa[mt][nt][1] *= c_lo;
                oa[mt][nt][2] *= c_hi; oa[mt][nt][3] *= c_hi;
            }
        }
        __syncwarp();

        // ---- PV MMA ----
        #pragma unroll
        for (int ks = 0; ks < 8; ks++) {
            int kk = ks * 8 + tig;
            float pa[2][4];
            #pragma unroll
            for (int mt = 0; mt < 2; mt++) {
                int r0 = mt * 16 + gid;
                pa[mt][0] = WSw[r0 * WSTRIDE + kk];
                pa[mt][1] = WSw[(r0 + 8) * WSTRIDE + kk];
                pa[mt][2] = WSw[r0 * WSTRIDE + kk + 4];
                pa[mt][3] = WSw[(r0 + 8) * WSTRIDE + kk + 4];
            }
            #pragma unroll
            for (int nt = 0; nt < 4; nt++) {
                int col = nt * 8 + gid;
                float bb[2];
                bb[0] = Vs[kk * 36 + col];
                bb[1] = Vs[(kk + 4) * 36 + col];
                #pragma unroll
                for (int mt = 0; mt < 2; mt++)
                    mma_tf32(oa[mt][nt], pa[mt], bb);
            }
        }

        // ---- commit prefetched tile to smem ----
        if (more) {
            __syncthreads();    // all warps done reading Ks/Vs/Rs/Mk
            #pragma unroll
            for (int j = 0; j < 4; j++) {
                int r = kvr + j * 16;
                Ks[(kvd + 0) * 68 + r] = f2tf(rK[j].x);
                Ks[(kvd + 1) * 68 + r] = f2tf(rK[j].y);
                Ks[(kvd + 2) * 68 + r] = f2tf(rK[j].z);
                Ks[(kvd + 3) * 68 + r] = f2tf(rK[j].w);
                float4 z;
                z.x = f2tf(rV[j].x); z.y = f2tf(rV[j].y);
                z.z = f2tf(rV[j].z); z.w = f2tf(rV[j].w);
                *(float4*)&Vs[r * 36 + kvd] = z;
            }
            #pragma unroll
            for (int j = 0; j < 12; j++) {
                int i = t + j * 128;
                int row = i >> 3, d0 = (i & 7) * 4;
                Rs[(d0 + 0) * 200 + row] = f2tf(rR[j].x);
                Rs[(d0 + 1) * 200 + row] = f2tf(rR[j].y);
                Rs[(d0 + 2) * 200 + row] = f2tf(rR[j].z);
                Rs[(d0 + 3) * 200 + row] = f2tf(rR[j].w);
            }
            if (t < 64) Mk[t] = rM;
            __syncthreads();    // new tile visible
        }
    }

    // ---- finalize ----
    #pragma unroll
    for (int mt = 0; mt < 2; mt++) {
        float inv_lo = (lss[mt][0] > 0.f) ? 1.f / lss[mt][0] : 0.f;
        float inv_hi = (lss[mt][1] > 0.f) ? 1.f / lss[mt][1] : 0.f;
        const int rlo = b * NS + q0 + w * 32 + mt * 16 + gid;
        #pragma unroll
        for (int nt = 0; nt < 4; nt++) {
            int col = h * NDK + nt * 8 + 2 * tig;
            out[(size_t)rlo * ND + col]           = oa[mt][nt][0] * inv_lo;
            out[(size_t)rlo * ND + col + 1]       = oa[mt][nt][1] * inv_lo;
            out[(size_t)(rlo + 8) * ND + col]     = oa[mt][nt][2] * inv_hi;
            out[(size_t)(rlo + 8) * ND + col + 1] = oa[mt][nt][3] * inv_hi;
        }
    }
}

// ---------------- pooling ----------------
__global__ void pool_score_kernel(const float* __restrict__ tmp, const float* __restrict__ pw2,
                                  const float* __restrict__ pb2, float* __restrict__ scores) {
    int gid = blockIdx.x * (blockDim.x >> 5) + (threadIdx.x >> 5);
    if (gid >= 4 * NBS) return;
    int head = gid / NBS;
    int row  = gid - head * NBS;
    int lane = threadIdx.x & 31;
    const float* p = tmp + (size_t)row * 384 + head * 96;
    float s = 0.f;
    for (int j = lane; j < 96; j += 32) s += p[j] * pw2[head * 96 + j];
    #pragma unroll
    for (int o = 16; o > 0; o >>= 1) s += __shfl_xor_sync(0xffffffffu, s, o);
    if (lane == 0) scores[gid] = s + pb2[head];
}

__global__ void pool_kernel(const float* __restrict__ x, const float* __restrict__ scores,
                            const int* __restrict__ ids, float* __restrict__ pooled) {
    const int head = blockIdx.x;
    const int b    = blockIdx.y;
    __shared__ float ps[NS];
    __shared__ float red[8];
    const float* sc = scores + (size_t)head * NBS + (size_t)b * NS;

    float m = -INFINITY;
    for (int s = threadIdx.x; s < NS; s += 256) {
        float val = (ids[b * NS + s] == 0) ? -INFINITY : sc[s];
        ps[s] = val;
        m = fmaxf(m, val);
    }
    #pragma unroll
    for (int o = 16; o > 0; o >>= 1) m = fmaxf(m, __shfl_xor_sync(0xffffffffu, m, o));
    if ((threadIdx.x & 31) == 0) red[threadIdx.x >> 5] = m;
    __syncthreads();
    float M = -INFINITY;
    #pragma unroll
    for (int i = 0; i < 8; i++) M = fmaxf(M, red[i]);
    __syncthreads();

    float sum = 0.f;
    for (int s = threadIdx.x; s < NS; s += 256) {
        float p = __expf(ps[s] - M);
        ps[s] = p;
        sum += p;
    }
    #pragma unroll
    for (int o = 16; o > 0; o >>= 1) sum += __shfl_xor_sync(0xffffffffu, sum, o);
    if ((threadIdx.x & 31) == 0) red[threadIdx.x >> 5] = sum;
    __syncthreads();
    float T = 0.f;
    #pragma unroll
    for (int i = 0; i < 8; i++) T += red[i];
    __syncthreads();
    float inv = 1.f / T;

    for (int d = threadIdx.x; d < ND; d += 256) {
        float acc = 0.f;
        const float* xp = x + (size_t)b * NS * ND + d;
        for (int s = 0; s < NS; s++) acc += ps[s] * xp[(size_t)s * ND];
        pooled[(size_t)b * (4 * ND) + head * ND + d] = acc * inv;
    }
}

// ---------------- dispatchers ----------------
static void run_big_gemm(const float* A, const float* W, const float* bias, const float* res,
                         float* C, int M, int N, int K, int epi) {
    dim3 grid(N / 128, M / 256);
    switch (epi) {
        case 0: gemm_tc_kernel<0><<<grid, 256, GEMM_SMEM_BYTES>>>(A, W, bias, res, C, M, N, K); break;
        case 1: gemm_tc_kernel<1><<<grid, 256, GEMM_SMEM_BYTES>>>(A, W, bias, res, C, M, N, K); break;
        case 2: gemm_tc_kernel<2><<<grid, 256, GEMM_SMEM_BYTES>>>(A, W, bias, res, C, M, N, K); break;
        case 3: gemm_tc_kernel<3><<<grid, 256, GEMM_SMEM_BYTES>>>(A, W, bias, res, C, M, N, K); break;
    }
}

static void run_small_gemm(const float* A, const float* W, const float* bias,
                           float* C, int M, int N, int K, int epi) {
    dim3 grid((N + 63) / 64, (M + 63) / 64);
    switch (epi) {
        case 0: gemm_kernel<0><<<grid, 256>>>(A, W, bias, C, M, N, K); break;
        case 1: gemm_kernel<1><<<grid, 256>>>(A, W, bias, C, M, N, K); break;
        case 3: gemm_kernel<3><<<grid, 256>>>(A, W, bias, C, M, N, K); break;
    }
}

// ---------------- entry ----------------
extern "C" void kernel_launch(void* const* d_in, const int* in_sizes, int n_in,
                              void* d_out, int out_size) {
    const float* te   = (const float*)d_in[0];
    const float* pe   = (const float*)d_in[1];
    const float* wq   = (const float*)d_in[2];
    const float* bq   = (const float*)d_in[3];
    const float* wk   = (const float*)d_in[4];
    const float* bk   = (const float*)d_in[5];
    const float* wv   = (const float*)d_in[6];
    const float* bv   = (const float*)d_in[7];
    const float* wo   = (const float*)d_in[8];
    const float* bo   = (const float*)d_in[9];
    const float* rel  = (const float*)d_in[10];
    const float* g1   = (const float*)d_in[11];
    const float* b1   = (const float*)d_in[12];
    const float* g2   = (const float*)d_in[13];
    const float* b2   = (const float*)d_in[14];
    const float* fw1  = (const float*)d_in[15];
    const float* fb1  = (const float*)d_in[16];
    const float* fw2  = (const float*)d_in[17];
    const float* fb2  = (const float*)d_in[18];
    const float* fg   = (const float*)d_in[19];
    const float* fbn  = (const float*)d_in[20];
    const float* pw1  = (const float*)d_in[21];
    const float* pb1  = (const float*)d_in[22];
    const float* pw2  = (const float*)d_in[23];
    const float* pb2  = (const float*)d_in[24];
    const float* cw1  = (const float*)d_in[25];
    const float* cb1  = (const float*)d_in[26];
    const float* cw2  = (const float*)d_in[27];
    const float* cb2  = (const float*)d_in[28];
    const float* cw3  = (const float*)d_in[29];
    const float* cb3  = (const float*)d_in[30];
    const int*   ids  = (const int*)d_in[31];

    float* S;
    cudaGetSymbolAddress((void**)&S, g_scratch);
    float* X    = S + OFF_X;
    float* HB   = S + OFF_H;
    float* QKV  = S + OFF_QKV;
    float* AB   = S + OFF_A;
    float* FB   = S + OFF_FF;
    float* PT   = S + OFF_PT;
    float* PS   = S + OFF_PS;
    float* PD   = S + OFF_PD;
    float* C1   = S + OFF_C1;
    float* C2   = S + OFF_C2;
    float* PW   = S + OFF_PW;
    float* WQKV = S + OFF_WQKV;
    float* BQKV = S + OFF_BQKV;

    cudaFuncSetAttribute(attn_tc_kernel,
                         cudaFuncAttributeMaxDynamicSharedMemorySize, ATT_SMEM_BYTES);
    cudaFuncSetAttribute(gemm_tc_kernel<0>,
                         cudaFuncAttributeMaxDynamicSharedMemorySize, GEMM_SMEM_BYTES);
    cudaFuncSetAttribute(gemm_tc_kernel<1>,
                         cudaFuncAttributeMaxDynamicSharedMemorySize, GEMM_SMEM_BYTES);
    cudaFuncSetAttribute(gemm_tc_kernel<2>,
                         cudaFuncAttributeMaxDynamicSharedMemorySize, GEMM_SMEM_BYTES);
    cudaFuncSetAttribute(gemm_tc_kernel<3>,
                         cudaFuncAttributeMaxDynamicSharedMemorySize, GEMM_SMEM_BYTES);

    pack_qkv_w<<<(NL * ND * QLD + 255) / 256, 256>>>(wq, wk, wv, WQKV);
    pack_qkv_b<<<(NL * QLD + 255) / 256, 256>>>(bq, bk, bv, BQKV);
    pack_pool_w<<<576, 256>>>(pw1, PW);

    embed_kernel<<<NBS, 128>>>(te, pe, ids, X);

    for (int l = 0; l < NL; l++) {
        const size_t wOff = (size_t)l * ND * ND;
        const size_t dOff = (size_t)l * ND;
        ln_kernel<<<NBS / 8, 256>>>(X, HB, g1 + dOff, b1 + dOff);
        run_big_gemm(HB, WQKV + (size_t)l * ND * QLD, BQKV + (size_t)l * QLD, nullptr,
                     QKV, NBS, QLD, ND, 0);
        attn_tc_kernel<<<dim3(NS / 128, NH, NB), 128, ATT_SMEM_BYTES>>>(
            QKV, QKV + ND, QKV + 2 * ND, rel + (size_t)l * (2 * NML - 1) * NDK, ids, AB);
        run_big_gemm(AB, wo + wOff, bo + dOff, X, X, NBS, ND, ND, 2);
        ln_kernel<<<NBS / 8, 256>>>(X, HB, g2 + dOff, b2 + dOff);
        run_big_gemm(HB, fw1 + (size_t)l * ND * NFF, fb1 + (size_t)l * NFF, nullptr, FB,
                     NBS, NFF, ND, 1);
        run_big_gemm(FB, fw2 + (size_t)l * NFF * ND, fb2 + dOff, X, X, NBS, ND, NFF, 2);
    }

    ln_kernel<<<NBS / 8, 256>>>(X, HB, fg, fbn);

    run_big_gemm(HB, PW, pb1, nullptr, PT, NBS, 384, 384, 3);
    pool_score_kernel<<<(4 * NBS + 3) / 4, 128>>>(PT, pw2, pb2, PS);
    pool_kernel<<<dim3(4, NB), 256>>>(HB, PS, ids, PD);

    run_small_gemm(PD, cw1, cb1, C1, NB, ND, 4 * ND, 1);
    run_small_gemm(C1, cw2, cb2, C2, NB, 192, ND, 1);
    run_small_gemm(C2, cw3, cb3, (float*)d_out, NB, NNC, 192, 0);
}